// round 1
// baseline (speedup 1.0000x reference)
#include <cuda_runtime.h>
#include <math.h>

#define NTOK 8192
#define HD   1024
#define NT   3
#define NE   6
#define NB   128
#define NC   64

// ---------------- scratch (device globals; no allocs allowed) ----------------
__device__ float g_t1[NTOK * HD];      // relu(encs@fc1 + b1)
__device__ float g_x[NTOK * HD];       // shared-bottom output
__device__ float g_glog[NTOK * 18];    // gate logits, [n][t*6+e]
__device__ float g_s[NTOK * 18];       // h[e,n]·v[e,t], [n][e*3+t]
__device__ float g_v[NE * NT * HD];    // v[e][t][f] = sum_o W2[e,f,o]*tw[t,o]
__device__ float g_c[18];              // c[e*3+t] = tw[t]·b2[e]
__device__ float g_maxs[NB * NT];      // per (b,t) max over candidates
__device__ float g_stats[37];          // [0..17] importance, [18..35] load, [36] bce sum

// ---------------- tiled SGEMM, 128x128x16, 8x8/thread, double-buffered -------
// MODE 0: C = relu(A@B + bias)   (bias per column)
// MODE 1: C = A@B + bias
// MODE 2: expert fused: h = relu(A@B[e] + bias[e]); S[n][e*3+t] += h·v[e,t]
//         (h never written; blockIdx.z = expert)
template <int MODE>
__global__ __launch_bounds__(256, 2)
void gemm128(const float* __restrict__ A, const float* __restrict__ B,
             const float* __restrict__ bias, float* __restrict__ C,
             const float* __restrict__ V, float* __restrict__ S,
             int M, int N, int K)
{
    const int e = blockIdx.z;
    if (MODE == 2) {
        B    += (size_t)e * K * N;
        bias += (size_t)e * N;
    }
    const int m0 = blockIdx.y * 128;
    const int n0 = blockIdx.x * 128;
    const int tid = threadIdx.x;
    const int tx = tid & 15, ty = tid >> 4;

    __shared__ float As[2][16][128];
    __shared__ float Bs[2][16][128];

    const float* Ab = A + (size_t)m0 * K;
    const float* Bb = B + n0;

    // A tile: 128 rows x 16 cols -> 512 float4, 2/thread (32B contiguous per thread)
    const int ar0 = (tid * 2) >> 2;
    const int ac0 = ((tid * 2) & 3) * 4;
    const int ar1 = (tid * 2 + 1) >> 2;
    const int ac1 = ((tid * 2 + 1) & 3) * 4;
    // B tile: 16 rows x 128 cols -> 512 float4, 2/thread
    const int br0 = (tid * 2) >> 5;
    const int bc0 = ((tid * 2) & 31) * 4;
    const int br1 = (tid * 2 + 1) >> 5;
    const int bc1 = ((tid * 2 + 1) & 31) * 4;

    float acc[8][8];
#pragma unroll
    for (int r = 0; r < 8; r++)
#pragma unroll
        for (int c = 0; c < 8; c++) acc[r][c] = 0.f;

    float4 a0, a1, b0, b1;

    // prologue: tile 0
    a0 = *(const float4*)(Ab + (size_t)ar0 * K + ac0);
    a1 = *(const float4*)(Ab + (size_t)ar1 * K + ac1);
    b0 = *(const float4*)(Bb + (size_t)br0 * N + bc0);
    b1 = *(const float4*)(Bb + (size_t)br1 * N + bc1);
    As[0][ac0 + 0][ar0] = a0.x; As[0][ac0 + 1][ar0] = a0.y;
    As[0][ac0 + 2][ar0] = a0.z; As[0][ac0 + 3][ar0] = a0.w;
    As[0][ac1 + 0][ar1] = a1.x; As[0][ac1 + 1][ar1] = a1.y;
    As[0][ac1 + 2][ar1] = a1.z; As[0][ac1 + 3][ar1] = a1.w;
    *(float4*)&Bs[0][br0][bc0] = b0;
    *(float4*)&Bs[0][br1][bc1] = b1;
    __syncthreads();

    const int KT = K / 16;
    int buf = 0;
    for (int kt = 0; kt < KT; kt++) {
        if (kt + 1 < KT) {
            const int ko = (kt + 1) * 16;
            a0 = *(const float4*)(Ab + (size_t)ar0 * K + ko + ac0);
            a1 = *(const float4*)(Ab + (size_t)ar1 * K + ko + ac1);
            b0 = *(const float4*)(Bb + (size_t)(ko + br0) * N + bc0);
            b1 = *(const float4*)(Bb + (size_t)(ko + br1) * N + bc1);
        }
#pragma unroll
        for (int kk = 0; kk < 16; kk++) {
            float ar[8], br[8];
            *(float4*)(ar)     = *(const float4*)&As[buf][kk][ty * 8];
            *(float4*)(ar + 4) = *(const float4*)&As[buf][kk][ty * 8 + 4];
            *(float4*)(br)     = *(const float4*)&Bs[buf][kk][tx * 8];
            *(float4*)(br + 4) = *(const float4*)&Bs[buf][kk][tx * 8 + 4];
#pragma unroll
            for (int r = 0; r < 8; r++)
#pragma unroll
                for (int c = 0; c < 8; c++)
                    acc[r][c] = fmaf(ar[r], br[c], acc[r][c]);
        }
        if (kt + 1 < KT) {
            const int nb = buf ^ 1;
            As[nb][ac0 + 0][ar0] = a0.x; As[nb][ac0 + 1][ar0] = a0.y;
            As[nb][ac0 + 2][ar0] = a0.z; As[nb][ac0 + 3][ar0] = a0.w;
            As[nb][ac1 + 0][ar1] = a1.x; As[nb][ac1 + 1][ar1] = a1.y;
            As[nb][ac1 + 2][ar1] = a1.z; As[nb][ac1 + 3][ar1] = a1.w;
            *(float4*)&Bs[nb][br0][bc0] = b0;
            *(float4*)&Bs[nb][br1][bc1] = b1;
            __syncthreads();
            buf = nb;
        }
    }

    float bv[8];
#pragma unroll
    for (int c = 0; c < 8; c++) bv[c] = bias[n0 + tx * 8 + c];

    if (MODE == 0 || MODE == 1) {
#pragma unroll
        for (int r = 0; r < 8; r++) {
            float* Crow = C + (size_t)(m0 + ty * 8 + r) * N + n0 + tx * 8;
            float out[8];
#pragma unroll
            for (int c = 0; c < 8; c++) {
                float vv = acc[r][c] + bv[c];
                if (MODE == 0) vv = fmaxf(vv, 0.f);
                out[c] = vv;
            }
            *(float4*)(Crow)     = *(float4*)(out);
            *(float4*)(Crow + 4) = *(float4*)(out + 4);
        }
    } else {
        // expert fused epilogue: p[r][t] = sum_c relu(acc+bias)*v[e][t][col]
        float vt[3][8];
#pragma unroll
        for (int t = 0; t < 3; t++)
#pragma unroll
            for (int c = 0; c < 8; c++)
                vt[t][c] = V[((size_t)e * 3 + t) * N + n0 + tx * 8 + c];
        float p[8][3];
#pragma unroll
        for (int r = 0; r < 8; r++) {
            p[r][0] = p[r][1] = p[r][2] = 0.f;
#pragma unroll
            for (int c = 0; c < 8; c++) {
                float h = fmaxf(acc[r][c] + bv[c], 0.f);
                p[r][0] = fmaf(h, vt[0][c], p[r][0]);
                p[r][1] = fmaf(h, vt[1][c], p[r][1]);
                p[r][2] = fmaf(h, vt[2][c], p[r][2]);
            }
        }
        // reduce across tx (lanes differ in low 4 bits of lane id)
#pragma unroll
        for (int off = 1; off < 16; off <<= 1)
#pragma unroll
            for (int r = 0; r < 8; r++)
#pragma unroll
                for (int t = 0; t < 3; t++)
                    p[r][t] += __shfl_xor_sync(0xffffffffu, p[r][t], off);
        if (tx == 0) {
#pragma unroll
            for (int r = 0; r < 8; r++)
#pragma unroll
                for (int t = 0; t < 3; t++)
                    atomicAdd(&S[(size_t)(m0 + ty * 8 + r) * 18 + e * 3 + t], p[r][t]);
        }
    }
}

// ---------------- v[e][t][f] = sum_o W2[e,f,o] * tw[t,o] ---------------------
__global__ void vker(const float* __restrict__ w2, const float* __restrict__ tw,
                     float* __restrict__ v)
{
    int w = (blockIdx.x * blockDim.x + threadIdx.x) >> 5;
    int lane = threadIdx.x & 31;
    if (w >= NE * NT * HD) return;
    int e = w / (NT * HD);
    int r = w % (NT * HD);
    int t = r / HD;
    int f = r % HD;
    const float* row = w2 + ((size_t)e * HD + f) * HD;
    const float* tv  = tw + (size_t)t * HD;
    float s = 0.f;
    for (int o = lane; o < HD; o += 32) s = fmaf(row[o], tv[o], s);
#pragma unroll
    for (int off = 16; off; off >>= 1) s += __shfl_xor_sync(0xffffffffu, s, off);
    if (lane == 0) v[w] = s;
}

// ---------------- c[e*3+t] = tw[t] · b2[e] ----------------------------------
__global__ void cker(const float* __restrict__ b2, const float* __restrict__ tw,
                     float* __restrict__ c)
{
    int w = threadIdx.x >> 5;
    int lane = threadIdx.x & 31;
    if (w >= 18) return;
    int e = w / 3, t = w % 3;
    float s = 0.f;
    for (int o = lane; o < HD; o += 32)
        s = fmaf(b2[(size_t)e * HD + o], tw[(size_t)t * HD + o], s);
#pragma unroll
    for (int off = 16; off; off >>= 1) s += __shfl_xor_sync(0xffffffffu, s, off);
    if (lane == 0) c[w] = s;
}

// ---------------- per-(b,t) max over candidates ------------------------------
__global__ void maxs_kernel(const float* __restrict__ scores, float* __restrict__ maxs)
{
    int i = threadIdx.x;
    if (i >= NB * NT) return;
    int b = i / NT, t = i % NT;
    float m = -1e30f;
    for (int cdx = 0; cdx < NC; cdx++)
        m = fmaxf(m, scores[(size_t)b * NC * NT + cdx * NT + t]);
    maxs[i] = m;
}

// ---------------- gate logits: glog[n][t*6+e] = x[n]·wg[t,:,e] --------------
// wgate staged into smem in [h][t*6+e] layout, 512-h halves (36KB static smem)
__global__ void glog_kernel(const float* __restrict__ x, const float* __restrict__ wg,
                            float* __restrict__ glog)
{
    __shared__ float wgs[512 * 18];
    const int tid = threadIdx.x, lane = tid & 31, w = tid >> 5;
    for (int p = 0; p < 2; p++) {
        const int hb = p * 512;
        __syncthreads();
        for (int idx = tid; idx < 512 * 18; idx += blockDim.x) {
            int h = idx / 18, j = idx % 18;
            int t = j / 6, e = j % 6;
            wgs[idx] = wg[(size_t)t * HD * NE + (size_t)(hb + h) * NE + e];
        }
        __syncthreads();
        for (int i = 0; i < 16; i++) {
            int n = blockIdx.x * 128 + i * 8 + w;
            float acc[18];
#pragma unroll
            for (int j = 0; j < 18; j++) acc[j] = 0.f;
            const float* xr = x + (size_t)n * HD + hb;
            for (int h = lane; h < 512; h += 32) {
                float xv = xr[h];
                const float* ws = &wgs[h * 18];
#pragma unroll
                for (int j = 0; j < 18; j++) acc[j] = fmaf(xv, ws[j], acc[j]);
            }
#pragma unroll
            for (int j = 0; j < 18; j++) {
#pragma unroll
                for (int off = 16; off; off >>= 1)
                    acc[j] += __shfl_xor_sync(0xffffffffu, acc[j], off);
            }
            if (lane == 0) {
                float* o = glog + (size_t)n * 18;
                if (p == 0) {
#pragma unroll
                    for (int j = 0; j < 18; j++) o[j] = acc[j];
                } else {
#pragma unroll
                    for (int j = 0; j < 18; j++) o[j] += acc[j];
                }
            }
        }
    }
}

// ---------------- per-token: top3/softmax, z, BCE, preds, imp/load ----------
__global__ void token_kernel(const float* __restrict__ glog, const float* __restrict__ s,
                             const float* __restrict__ c, const float* __restrict__ scores,
                             const float* __restrict__ maxs, const float* __restrict__ tb,
                             float* __restrict__ stats, float* __restrict__ preds)
{
    __shared__ float simp[18], sld[18], red[256];
    const int tid = threadIdx.x;
    if (tid < 18) { simp[tid] = 0.f; sld[tid] = 0.f; }
    __syncthreads();

    const int n = blockIdx.x * 256 + tid;
    const int b = n >> 6, cdx = n & 63;

    float l[18];
    const float* gl = glog + (size_t)n * 18;
#pragma unroll
    for (int j = 0; j < 18; j++) l[j] = gl[j];
    const float* sr = s + (size_t)n * 18;

    float bsum = 0.f, zsum = 0.f;
#pragma unroll
    for (int t = 0; t < 3; t++) {
        const float* lt = l + t * 6;
        // top-3 of 6, jax tie-break = lower index wins
        float sv0 = 0, sv1 = 0, sv2 = 0;
        int se0 = 0, se1 = 0, se2 = 0, cnt = 0;
#pragma unroll
        for (int e = 0; e < 6; e++) {
            int beats = 0;
#pragma unroll
            for (int j = 0; j < 6; j++)
                beats += (lt[j] > lt[e]) || (lt[j] == lt[e] && j < e);
            if (beats < 3) {
                if (cnt == 0)      { sv0 = lt[e]; se0 = e; }
                else if (cnt == 1) { sv1 = lt[e]; se1 = e; }
                else               { sv2 = lt[e]; se2 = e; }
                cnt++;
            }
        }
        float m  = fmaxf(sv0, fmaxf(sv1, sv2));
        float g0 = expf(sv0 - m), g1 = expf(sv1 - m), g2 = expf(sv2 - m);
        float inv = 1.f / (g0 + g1 + g2);
        g0 *= inv; g1 *= inv; g2 *= inv;

        float zt = tb[t];
        zt = fmaf(g0, sr[se0 * 3 + t] + c[se0 * 3 + t], zt);
        zt = fmaf(g1, sr[se1 * 3 + t] + c[se1 * 3 + t], zt);
        zt = fmaf(g2, sr[se2 * 3 + t] + c[se2 * 3 + t], zt);

        atomicAdd(&simp[t * 6 + se0], g0);
        atomicAdd(&simp[t * 6 + se1], g1);
        atomicAdd(&simp[t * 6 + se2], g2);
        atomicAdd(&sld[t * 6 + se0], 1.f);
        atomicAdd(&sld[t * 6 + se1], 1.f);
        atomicAdd(&sld[t * 6 + se2], 1.f);

        float sc  = scores[(size_t)b * NC * NT + cdx * NT + t];
        float lab = (sc == maxs[b * NT + t]) ? 1.f : 0.f;
        bsum += fmaxf(zt, 0.f) - zt * lab + log1pf(expf(-fabsf(zt)));
        zsum += zt;
    }
    preds[n] = 1.f / (1.f + expf(-zsum * (1.f / 3.f)));

    red[tid] = bsum;
    __syncthreads();
    for (int off = 128; off; off >>= 1) {
        if (tid < off) red[tid] += red[tid + off];
        __syncthreads();
    }
    if (tid == 0) atomicAdd(&stats[36], red[0]);
    if (tid < 18) {
        atomicAdd(&stats[tid], simp[tid]);
        atomicAdd(&stats[18 + tid], sld[tid]);
    }
}

// ---------------- final scalar: loss = bce + 1e-2 * sum cv^2 -----------------
__global__ void final_kernel(const float* __restrict__ stats, float* __restrict__ out)
{
    if (threadIdx.x == 0) {
        float aux = 0.f;
        for (int t = 0; t < 3; t++) {
            for (int which = 0; which < 2; which++) {
                const float* v = stats + which * 18 + t * 6;
                float mean = 0.f;
                for (int e = 0; e < 6; e++) mean += v[e];
                mean *= (1.f / 6.f);
                float var = 0.f;
                for (int e = 0; e < 6; e++) {
                    float d = v[e] - mean;
                    var += d * d;
                }
                var *= (1.f / 5.f);  // ddof=1
                aux += var / (mean * mean + 1e-10f);
            }
        }
        out[0] = stats[36] * (1.f / (NB * NC * NT)) + 0.01f * aux;
    }
}

// -----------------------------------------------------------------------------
extern "C" void kernel_launch(void* const* d_in, const int* in_sizes, int n_in,
                              void* d_out, int out_size)
{
    const float* encs   = (const float*)d_in[0];
    const float* scores = (const float*)d_in[1];
    const float* fc1_w  = (const float*)d_in[2];
    const float* fc1_b  = (const float*)d_in[3];
    const float* fc2_w  = (const float*)d_in[4];
    const float* fc2_b  = (const float*)d_in[5];
    const float* w_gate = (const float*)d_in[6];
    const float* ew1    = (const float*)d_in[7];
    const float* eb1    = (const float*)d_in[8];
    const float* ew2    = (const float*)d_in[9];
    const float* eb2    = (const float*)d_in[10];
    const float* tw     = (const float*)d_in[11];
    const float* tb     = (const float*)d_in[12];

    float *t1, *x, *glog, *s, *v, *c, *maxs, *stats;
    cudaGetSymbolAddress((void**)&t1, g_t1);
    cudaGetSymbolAddress((void**)&x, g_x);
    cudaGetSymbolAddress((void**)&glog, g_glog);
    cudaGetSymbolAddress((void**)&s, g_s);
    cudaGetSymbolAddress((void**)&v, g_v);
    cudaGetSymbolAddress((void**)&c, g_c);
    cudaGetSymbolAddress((void**)&maxs, g_maxs);
    cudaGetSymbolAddress((void**)&stats, g_stats);

    float* outf  = (float*)d_out;
    float* preds = outf + (out_size - NTOK);  // loss (if present) precedes preds

    cudaMemsetAsync(s, 0, (size_t)NTOK * 18 * sizeof(float), 0);
    cudaMemsetAsync(stats, 0, 37 * sizeof(float), 0);

    // shared bottom
    gemm128<0><<<dim3(8, 64, 1), 256>>>(encs, fc1_w, fc1_b, t1, nullptr, nullptr,
                                        NTOK, HD, HD);
    gemm128<1><<<dim3(8, 64, 1), 256>>>(t1, fc2_w, fc2_b, x, nullptr, nullptr,
                                        NTOK, HD, HD);
    // small precomputes (independent)
    vker<<<(NE * NT * HD * 32 + 255) / 256, 256>>>(ew2, tw, v);
    cker<<<1, 576>>>(eb2, tw, c);
    maxs_kernel<<<1, 384>>>(scores, maxs);
    // gate logits
    glog_kernel<<<64, 256>>>(x, w_gate, glog);
    // 6 experts, layer-1 GEMM fused with tower-projected reduction (layer-2 eliminated)
    gemm128<2><<<dim3(8, 64, 6), 256>>>(x, ew1, eb1, nullptr, v, s, NTOK, HD, HD);
    // per-token gating + loss terms + preds
    token_kernel<<<32, 256>>>(glog, s, c, scores, maxs, tb, stats, preds);
    if (out_size > NTOK) final_kernel<<<1, 32>>>(stats, outf);
}

// round 4
// speedup vs baseline: 1.5553x; 1.5553x over previous
#include <cuda_runtime.h>
#include <math.h>
#include <stdint.h>
#include <mma.h>

using namespace nvcuda;

#define NTOK 8192
#define HD   1024
#define NT   3
#define NE   6
#define NB   128
#define NC   64

// GEMM tiling
#define BM 128
#define BN 128
#define BK 32
#define KT (HD / BK)
#define LDA 40                       // 32 + 8 pad (multiple of 8)
#define LDB 136                      // 128 + 8 pad (multiple of 8)
#define ABUF (BM * LDA)              // 5120 floats
#define BBUF (BK * LDB)              // 4352 floats
#define BUFFLOATS (ABUF + BBUF)      // 9472 floats
#define SMEM_FLOATS (2 * BUFFLOATS)  // 18944 floats = 75776 B
#define SMEM_BYTES (SMEM_FLOATS * 4)

// ---------------- scratch (device globals; no allocs allowed) ----------------
__device__ float g_t1[NTOK * HD];      // relu(encs@fc1 + b1)
__device__ float g_x[NTOK * HD];       // shared-bottom output
__device__ float g_glog[NTOK * 18];    // gate logits, [n][t*6+e]
__device__ float g_s[NTOK * 18];       // h[e,n]·v[e,t], [n][e*3+t]
__device__ float g_v[NE * NT * HD];    // v[e][t][f] = sum_o W2[e,f,o]*tw[t,o]
__device__ float g_c[18];              // c[e*3+t] = tw[t]·b2[e]
__device__ float g_maxs[NB * NT];      // per (b,t) max over candidates
__device__ float g_stats[37];          // [0..17] importance, [18..35] load, [36] bce sum

// ---------------- cp.async helpers ------------------------------------------
__device__ __forceinline__ uint32_t smem_u32(const void* p) {
    uint32_t a;
    asm("{ .reg .u64 t; cvta.to.shared.u64 t, %1; cvt.u32.u64 %0, t; }"
        : "=r"(a) : "l"(p));
    return a;
}
#define CP16(dst_u32, src) \
    asm volatile("cp.async.cg.shared.global [%0], [%1], 16;" \
                 :: "r"(dst_u32), "l"(src) : "memory")
#define CPCOMMIT() asm volatile("cp.async.commit_group;" ::: "memory")
#define CPWAIT(n)  asm volatile("cp.async.wait_group %0;" :: "n"(n) : "memory")

// ======================= wmma tf32 GEMM ======================================
// CTA 128x128, K-chunks of 32, cp.async double buffer.
// 8 warps: wm = wid&1 (64 rows), wn = wid>>1 (32 cols); 4x2 wmma 16x16x8 frags.
// A: [M,K] row-major fp32 (tokens).  B: [K,N] row-major fp32 (original weights).
// MODE 0: C = relu(A@B + bias); MODE 1: C = A@B + bias
// MODE 2: h = relu(A@B[e] + b1[e]); S[n][e*3+t] += h · v[e][t]   (h not stored)
template <int MODE>
__global__ __launch_bounds__(256)
void wgemm(const float* __restrict__ A, const float* __restrict__ B,
           const float* __restrict__ bias, float* __restrict__ C,
           const float* __restrict__ V, float* __restrict__ S)
{
    extern __shared__ float sm[];
    const int e = blockIdx.z;
    if (MODE == 2) { B += (size_t)e * HD * HD; bias += (size_t)e * HD; }
    const int m0 = blockIdx.y * BM;
    const int n0 = blockIdx.x * BN;
    const int tid = threadIdx.x;
    const int wid = tid >> 5;
    const int wm = wid & 1;        // 0..1 -> 64-row slab
    const int wn = wid >> 1;       // 0..3 -> 32-col slab

    const uint32_t sm_u = smem_u32(sm);

    // per-thread load geometry
    const int ar = tid >> 3, ac = (tid & 7) * 4;    // A: 32 rows/round, 8 f4 per row
    const int br = tid >> 5, bc = (tid & 31) * 4;   // B: 8 rows/round, 32 f4 per row

    wmma::fragment<wmma::accumulator, 16, 16, 8, float> cf[4][2];
#pragma unroll
    for (int i = 0; i < 4; i++)
#pragma unroll
        for (int j = 0; j < 2; j++) wmma::fill_fragment(cf[i][j], 0.0f);

    // prologue: chunk 0 -> buffer 0
    {
        const float* Asrc = A + (size_t)(m0 + ar) * HD + ac;
        const float* Bsrc = B + (size_t)br * HD + n0 + bc;
        uint32_t sa = sm_u, sb = sm_u + ABUF * 4;
#pragma unroll
        for (int j = 0; j < 4; j++)
            CP16(sa + ((ar + j * 32) * LDA + ac) * 4, Asrc + (size_t)j * 32 * HD);
#pragma unroll
        for (int j = 0; j < 4; j++)
            CP16(sb + ((br + j * 8) * LDB + bc) * 4, Bsrc + (size_t)j * 8 * HD);
        CPCOMMIT();
    }

    int buf = 0;
    for (int kt = 0; kt < KT; kt++) {
        if (kt + 1 < KT) {
            const int k0 = (kt + 1) * BK;
            const float* Asrc = A + (size_t)(m0 + ar) * HD + k0 + ac;
            const float* Bsrc = B + (size_t)(k0 + br) * HD + n0 + bc;
            uint32_t base = sm_u + (buf ^ 1) * BUFFLOATS * 4;
            uint32_t sa = base, sb = base + ABUF * 4;
#pragma unroll
            for (int j = 0; j < 4; j++)
                CP16(sa + ((ar + j * 32) * LDA + ac) * 4, Asrc + (size_t)j * 32 * HD);
#pragma unroll
            for (int j = 0; j < 4; j++)
                CP16(sb + ((br + j * 8) * LDB + bc) * 4, Bsrc + (size_t)j * 8 * HD);
            CPCOMMIT();
            CPWAIT(1);
        } else {
            CPWAIT(0);
        }
        __syncthreads();

        const float* sa = sm + buf * BUFFLOATS;
        const float* sb = sa + ABUF;
        const float* Abase = sa + (wm * 64) * LDA;
        const float* Bbase = sb + wn * 32;
#pragma unroll
        for (int kk = 0; kk < 4; kk++) {
            wmma::fragment<wmma::matrix_a, 16, 16, 8, wmma::precision::tf32,
                           wmma::row_major> af[4];
            wmma::fragment<wmma::matrix_b, 16, 16, 8, wmma::precision::tf32,
                           wmma::row_major> bf[2];
#pragma unroll
            for (int i = 0; i < 4; i++) {
                wmma::load_matrix_sync(af[i], Abase + i * 16 * LDA + kk * 8, LDA);
#pragma unroll
                for (int q = 0; q < af[i].num_elements; q++)
                    af[i].x[q] = wmma::__float_to_tf32(af[i].x[q]);
            }
#pragma unroll
            for (int j = 0; j < 2; j++) {
                wmma::load_matrix_sync(bf[j], Bbase + kk * 8 * LDB + j * 16, LDB);
#pragma unroll
                for (int q = 0; q < bf[j].num_elements; q++)
                    bf[j].x[q] = wmma::__float_to_tf32(bf[j].x[q]);
            }
#pragma unroll
            for (int i = 0; i < 4; i++)
#pragma unroll
                for (int j = 0; j < 2; j++)
                    wmma::mma_sync(cf[i][j], af[i], bf[j], cf[i][j]);
        }
        __syncthreads();
        buf ^= 1;
    }

    // ---- epilogue: dump accumulators into smem C tile (128x128, ld=128) ----
    float* cb = sm;
#pragma unroll
    for (int i = 0; i < 4; i++)
#pragma unroll
        for (int j = 0; j < 2; j++)
            wmma::store_matrix_sync(cb + (wm * 64 + i * 16) * 128 + wn * 32 + j * 16,
                                    cf[i][j], 128, wmma::mem_row_major);

    float* sbias = sm + 128 * 128;
    if (tid < 128) sbias[tid] = bias[n0 + tid];
    float* sv = sbias + 128;
    if (MODE == 2) {
        for (int j = tid; j < 384; j += 256)
            sv[j] = V[((size_t)e * 3 + (j >> 7)) * HD + n0 + (j & 127)];
    }
    __syncthreads();

    if (MODE < 2) {
#pragma unroll
        for (int j = 0; j < 16; j++) {
            int i = tid + 256 * j;
            int r = i >> 5, col = (i & 31) * 4;
            float out[4];
#pragma unroll
            for (int q = 0; q < 4; q++) {
                float v = cb[r * 128 + col + q] + sbias[col + q];
                out[q] = (MODE == 0) ? fmaxf(v, 0.0f) : v;
            }
            *(float4*)(C + (size_t)(m0 + r) * HD + n0 + col) = *(float4*)out;
        }
    } else {
        const int row = tid >> 1, half = (tid & 1) * 64;
        float p0 = 0.f, p1 = 0.f, p2 = 0.f;
        const float* crow = cb + row * 128 + half;
#pragma unroll 16
        for (int col = 0; col < 64; col++) {
            float h = fmaxf(crow[col] + sbias[half + col], 0.0f);
            p0 = fmaf(h, sv[half + col],       p0);
            p1 = fmaf(h, sv[128 + half + col], p1);
            p2 = fmaf(h, sv[256 + half + col], p2);
        }
        p0 += __shfl_xor_sync(0xffffffffu, p0, 1);
        p1 += __shfl_xor_sync(0xffffffffu, p1, 1);
        p2 += __shfl_xor_sync(0xffffffffu, p2, 1);
        if (!(tid & 1)) {
            float* Sp = S + (size_t)(m0 + row) * 18 + e * 3;
            atomicAdd(Sp + 0, p0);
            atomicAdd(Sp + 1, p1);
            atomicAdd(Sp + 2, p2);
        }
    }
}

// ---------------- v[e][t][f] = sum_o W2[e,f,o] * tw[t,o] ---------------------
__global__ void vker(const float* __restrict__ w2, const float* __restrict__ tw,
                     float* __restrict__ v)
{
    int w = (blockIdx.x * blockDim.x + threadIdx.x) >> 5;
    int lane = threadIdx.x & 31;
    if (w >= NE * NT * HD) return;
    int e = w / (NT * HD);
    int r = w % (NT * HD);
    int t = r / HD;
    int f = r % HD;
    const float* row = w2 + ((size_t)e * HD + f) * HD;
    const float* tv  = tw + (size_t)t * HD;
    float s = 0.f;
    for (int o = lane; o < HD; o += 32) s = fmaf(row[o], tv[o], s);
#pragma unroll
    for (int off = 16; off; off >>= 1) s += __shfl_xor_sync(0xffffffffu, s, off);
    if (lane == 0) v[w] = s;
}

// ---------------- c[e*3+t] = tw[t] · b2[e] ----------------------------------
__global__ void cker(const float* __restrict__ b2, const float* __restrict__ tw,
                     float* __restrict__ c)
{
    int w = threadIdx.x >> 5;
    int lane = threadIdx.x & 31;
    if (w >= 18) return;
    int e = w / 3, t = w % 3;
    float s = 0.f;
    for (int o = lane; o < HD; o += 32)
        s = fmaf(b2[(size_t)e * HD + o], tw[(size_t)t * HD + o], s);
#pragma unroll
    for (int off = 16; off; off >>= 1) s += __shfl_xor_sync(0xffffffffu, s, off);
    if (lane == 0) c[w] = s;
}

// ---------------- per-(b,t) max over candidates ------------------------------
__global__ void maxs_kernel(const float* __restrict__ scores, float* __restrict__ maxs)
{
    int i = threadIdx.x;
    if (i >= NB * NT) return;
    int b = i / NT, t = i % NT;
    float m = -1e30f;
    for (int cdx = 0; cdx < NC; cdx++)
        m = fmaxf(m, scores[(size_t)b * NC * NT + cdx * NT + t]);
    maxs[i] = m;
}

// ---------------- gate logits: glog[n][t*6+e] = x[n]·wg[t,:,e] --------------
__global__ void glog_kernel(const float* __restrict__ x, const float* __restrict__ wg,
                            float* __restrict__ glog)
{
    __shared__ float wgs[512 * 18];
    const int tid = threadIdx.x, lane = tid & 31, w = tid >> 5;
    for (int p = 0; p < 2; p++) {
        const int hb = p * 512;
        __syncthreads();
        for (int idx = tid; idx < 512 * 18; idx += blockDim.x) {
            int h = idx / 18, j = idx % 18;
            int t = j / 6, ee = j % 6;
            wgs[idx] = wg[(size_t)t * HD * NE + (size_t)(hb + h) * NE + ee];
        }
        __syncthreads();
        for (int i = 0; i < 16; i++) {
            int n = blockIdx.x * 128 + i * 8 + w;
            float acc[18];
#pragma unroll
            for (int j = 0; j < 18; j++) acc[j] = 0.f;
            const float* xr = x + (size_t)n * HD + hb;
            for (int h = lane; h < 512; h += 32) {
                float xv = xr[h];
                const float* ws = &wgs[h * 18];
#pragma unroll
                for (int j = 0; j < 18; j++) acc[j] = fmaf(xv, ws[j], acc[j]);
            }
#pragma unroll
            for (int j = 0; j < 18; j++) {
#pragma unroll
                for (int off = 16; off; off >>= 1)
                    acc[j] += __shfl_xor_sync(0xffffffffu, acc[j], off);
            }
            if (lane == 0) {
                float* o = glog + (size_t)n * 18;
                if (p == 0) {
#pragma unroll
                    for (int j = 0; j < 18; j++) o[j] = acc[j];
                } else {
#pragma unroll
                    for (int j = 0; j < 18; j++) o[j] += acc[j];
                }
            }
        }
    }
}

// ---------------- per-token: top3/softmax, z, BCE, preds, imp/load ----------
__global__ void token_kernel(const float* __restrict__ glog, const float* __restrict__ s,
                             const float* __restrict__ c, const float* __restrict__ scores,
                             const float* __restrict__ maxs, const float* __restrict__ tb,
                             float* __restrict__ stats, float* __restrict__ preds)
{
    __shared__ float simp[18], sld[18], red[256];
    const int tid = threadIdx.x;
    if (tid < 18) { simp[tid] = 0.f; sld[tid] = 0.f; }
    __syncthreads();

    const int n = blockIdx.x * 256 + tid;
    const int b = n >> 6, cdx = n & 63;

    float l[18];
    const float* gl = glog + (size_t)n * 18;
#pragma unroll
    for (int j = 0; j < 18; j++) l[j] = gl[j];
    const float* sr = s + (size_t)n * 18;

    float bsum = 0.f, zsum = 0.f;
#pragma unroll
    for (int t = 0; t < 3; t++) {
        const float* lt = l + t * 6;
        float sv0 = 0, sv1 = 0, sv2 = 0;
        int se0 = 0, se1 = 0, se2 = 0, cnt = 0;
#pragma unroll
        for (int e = 0; e < 6; e++) {
            int beats = 0;
#pragma unroll
            for (int j = 0; j < 6; j++)
                beats += (lt[j] > lt[e]) || (lt[j] == lt[e] && j < e);
            if (beats < 3) {
                if (cnt == 0)      { sv0 = lt[e]; se0 = e; }
                else if (cnt == 1) { sv1 = lt[e]; se1 = e; }
                else               { sv2 = lt[e]; se2 = e; }
                cnt++;
            }
        }
        float m  = fmaxf(sv0, fmaxf(sv1, sv2));
        float g0 = expf(sv0 - m), g1 = expf(sv1 - m), g2 = expf(sv2 - m);
        float inv = 1.f / (g0 + g1 + g2);
        g0 *= inv; g1 *= inv; g2 *= inv;

        float zt = tb[t];
        zt = fmaf(g0, sr[se0 * 3 + t] + c[se0 * 3 + t], zt);
        zt = fmaf(g1, sr[se1 * 3 + t] + c[se1 * 3 + t], zt);
        zt = fmaf(g2, sr[se2 * 3 + t] + c[se2 * 3 + t], zt);

        atomicAdd(&simp[t * 6 + se0], g0);
        atomicAdd(&simp[t * 6 + se1], g1);
        atomicAdd(&simp[t * 6 + se2], g2);
        atomicAdd(&sld[t * 6 + se0], 1.f);
        atomicAdd(&sld[t * 6 + se1], 1.f);
        atomicAdd(&sld[t * 6 + se2], 1.f);

        float sc  = scores[(size_t)b * NC * NT + cdx * NT + t];
        float lab = (sc == maxs[b * NT + t]) ? 1.f : 0.f;
        bsum += fmaxf(zt, 0.f) - zt * lab + log1pf(expf(-fabsf(zt)));
        zsum += zt;
    }
    preds[n] = 1.f / (1.f + expf(-zsum * (1.f / 3.f)));

    red[tid] = bsum;
    __syncthreads();
    for (int off = 128; off; off >>= 1) {
        if (tid < off) red[tid] += red[tid + off];
        __syncthreads();
    }
    if (tid == 0) atomicAdd(&stats[36], red[0]);
    if (tid < 18) {
        atomicAdd(&stats[tid], simp[tid]);
        atomicAdd(&stats[18 + tid], sld[tid]);
    }
}

// ---------------- final scalar: loss = bce + 1e-2 * sum cv^2 -----------------
__global__ void final_kernel(const float* __restrict__ stats, float* __restrict__ out)
{
    if (threadIdx.x == 0) {
        float aux = 0.f;
        for (int t = 0; t < 3; t++) {
            for (int which = 0; which < 2; which++) {
                const float* v = stats + which * 18 + t * 6;
                float mean = 0.f;
                for (int e = 0; e < 6; e++) mean += v[e];
                mean *= (1.f / 6.f);
                float var = 0.f;
                for (int e = 0; e < 6; e++) {
                    float d = v[e] - mean;
                    var += d * d;
                }
                var *= (1.f / 5.f);
                aux += var / (mean * mean + 1e-10f);
            }
        }
        out[0] = stats[36] * (1.f / (NB * NC * NT)) + 0.01f * aux;
    }
}

// -----------------------------------------------------------------------------
extern "C" void kernel_launch(void* const* d_in, const int* in_sizes, int n_in,
                              void* d_out, int out_size)
{
    const float* encs   = (const float*)d_in[0];
    const float* scores = (const float*)d_in[1];
    const float* fc1_w  = (const float*)d_in[2];
    const float* fc1_b  = (const float*)d_in[3];
    const float* fc2_w  = (const float*)d_in[4];
    const float* fc2_b  = (const float*)d_in[5];
    const float* w_gate = (const float*)d_in[6];
    const float* ew1    = (const float*)d_in[7];
    const float* eb1    = (const float*)d_in[8];
    const float* ew2    = (const float*)d_in[9];
    const float* eb2    = (const float*)d_in[10];
    const float* tw     = (const float*)d_in[11];
    const float* tb     = (const float*)d_in[12];

    float *t1, *x, *glog, *s, *v, *c, *maxs, *stats;
    cudaGetSymbolAddress((void**)&t1, g_t1);
    cudaGetSymbolAddress((void**)&x, g_x);
    cudaGetSymbolAddress((void**)&glog, g_glog);
    cudaGetSymbolAddress((void**)&s, g_s);
    cudaGetSymbolAddress((void**)&v, g_v);
    cudaGetSymbolAddress((void**)&c, g_c);
    cudaGetSymbolAddress((void**)&maxs, g_maxs);
    cudaGetSymbolAddress((void**)&stats, g_stats);

    float* outf  = (float*)d_out;
    float* preds = outf + (out_size - NTOK);

    cudaFuncSetAttribute(wgemm<0>, cudaFuncAttributeMaxDynamicSharedMemorySize, SMEM_BYTES);
    cudaFuncSetAttribute(wgemm<1>, cudaFuncAttributeMaxDynamicSharedMemorySize, SMEM_BYTES);
    cudaFuncSetAttribute(wgemm<2>, cudaFuncAttributeMaxDynamicSharedMemorySize, SMEM_BYTES);

    cudaMemsetAsync(s, 0, (size_t)NTOK * 18 * sizeof(float), 0);
    cudaMemsetAsync(stats, 0, 37 * sizeof(float), 0);

    // small precomputes (independent of GEMMs)
    vker<<<(NE * NT * HD * 32 + 255) / 256, 256>>>(ew2, tw, v);
    cker<<<1, 576>>>(eb2, tw, c);
    maxs_kernel<<<1, 384>>>(scores, maxs);

    // shared bottom (wmma tf32)
    wgemm<0><<<dim3(8, 64, 1), 256, SMEM_BYTES>>>(encs, fc1_w, fc1_b, t1, nullptr, nullptr);
    wgemm<1><<<dim3(8, 64, 1), 256, SMEM_BYTES>>>(t1, fc2_w, fc2_b, x, nullptr, nullptr);
    // gate logits
    glog_kernel<<<64, 256>>>(x, w_gate, glog);
    // experts: layer-1 GEMM fused with tower-projected reduction (layer-2 eliminated)
    wgemm<2><<<dim3(8, 64, 6), 256, SMEM_BYTES>>>(x, ew1, eb1, nullptr, v, s);
    // per-token gating + loss + preds
    token_kernel<<<32, 256>>>(glog, s, c, scores, maxs, tb, stats, preds);
    if (out_size > NTOK) final_kernel<<<1, 32>>>(stats, outf);
}

// round 5
// speedup vs baseline: 5.0049x; 3.2180x over previous
#include <cuda_runtime.h>
#include <cuda_fp16.h>
#include <math.h>
#include <stdint.h>
#include <mma.h>

using namespace nvcuda;

#define NTOK 8192
#define HD   1024
#define NT   3
#define NE   6
#define NB   128
#define NC   64

// GEMM tiling (fp16 inputs, fp32 accumulate)
#define BM 128
#define BN 128
#define BK 64
#define KT (HD / BK)
#define LDA 72                        // 64 + 8 halves pad
#define LDB 136                       // 128 + 8 halves pad
#define ABUF_H (BM * LDA)             // 9216 halves
#define BBUF_H (BK * LDB)             // 8704 halves
#define BUF_H  (ABUF_H + BBUF_H)      // 17920 halves
#define SMEM_BYTES (2 * BUF_H * 2)    // 71680 B (also covers 67584 B epilogue)

// ---------------- scratch (device globals; no allocs allowed) ----------------
__device__ __half g_he[NTOK * HD];     // encs fp16
__device__ __half g_hw[8 * HD * HD];   // fp16 weights: [0]=fc1 [1]=fc2 [2..7]=ew1
__device__ __half g_t1h[NTOK * HD];    // relu(encs@fc1+b1) fp16
__device__ __half g_xh[NTOK * HD];     // shared-bottom out fp16
__device__ float g_glog[NTOK * 18];    // gate logits, [n][t*6+e]
__device__ float g_s[NTOK * 18];       // h[e,n]·v[e,t], [n][e*3+t]
__device__ float g_v[NE * NT * HD];    // v[e][t][f] = sum_o W2[e,f,o]*tw[t,o]
__device__ float g_c[18];              // c[e*3+t] = tw[t]·b2[e]
__device__ float g_maxs[NB * NT];      // per (b,t) max over candidates
__device__ float g_stats[37];          // [0..17] importance, [18..35] load, [36] bce

// ---------------- cp.async helpers ------------------------------------------
__device__ __forceinline__ uint32_t smem_u32(const void* p) {
    uint32_t a;
    asm("{ .reg .u64 t; cvta.to.shared.u64 t, %1; cvt.u32.u64 %0, t; }"
        : "=r"(a) : "l"(p));
    return a;
}
#define CP16(dst_u32, src) \
    asm volatile("cp.async.cg.shared.global [%0], [%1], 16;" \
                 :: "r"(dst_u32), "l"(src) : "memory")
#define CPCOMMIT() asm volatile("cp.async.commit_group;" ::: "memory")
#define CPWAIT(n)  asm volatile("cp.async.wait_group %0;" :: "n"(n) : "memory")

// ---------------- fp32 -> fp16 conversion -----------------------------------
__global__ void h2kern(const float* __restrict__ src, __half* __restrict__ dst, int n)
{
    int i = (blockIdx.x * blockDim.x + threadIdx.x) * 4;
    if (i < n) {
        float4 v = *(const float4*)(src + i);
        __half2 lo = __floats2half2_rn(v.x, v.y);
        __half2 hi = __floats2half2_rn(v.z, v.w);
        *(__half2*)(dst + i)     = lo;
        *(__half2*)(dst + i + 2) = hi;
    }
}

// ======================= fp16 wmma GEMM ======================================
// CTA 128x128, K-chunks of 64, cp.async double buffer, 2 CTAs/SM.
// 8 warps: wm = wid&1 (64 rows), wn = wid>>1 (32 cols); 4x2 wmma 16x16x16.
// A: half[M,K] row-major.  B: half[K,N] row-major.
// MODE 0: Ch = half(relu(A@B + bias));  MODE 1: Ch = half(A@B + bias)
// MODE 2: h = relu(A@B[e] + b1[e]); S[n][e*3+t] += h · v[e][t]  (h not stored)
template <int MODE>
__global__ __launch_bounds__(256, 2)
void wgemm(const __half* __restrict__ A, const __half* __restrict__ B,
           const float* __restrict__ bias, __half* __restrict__ Ch,
           const float* __restrict__ V, float* __restrict__ S)
{
    extern __shared__ char smraw[];
    __half* sm = (__half*)smraw;
    const int e = blockIdx.z;
    if (MODE == 2) { B += (size_t)e * HD * HD; bias += (size_t)e * HD; }
    const int m0 = blockIdx.y * BM;
    const int n0 = blockIdx.x * BN;
    const int tid = threadIdx.x;
    const int wid = tid >> 5;
    const int wm = wid & 1;        // 64-row slab
    const int wn = wid >> 1;       // 32-col slab
    const uint32_t sm_u = smem_u32(sm);

    wmma::fragment<wmma::accumulator, 16, 16, 16, float> cf[4][2];
#pragma unroll
    for (int i = 0; i < 4; i++)
#pragma unroll
        for (int j = 0; j < 2; j++) wmma::fill_fragment(cf[i][j], 0.0f);

    // load geometry: A 128 rows x 8 chunks(16B) ; B 64 rows x 16 chunks
    // prologue: chunk 0 -> buffer 0
    {
        uint32_t sa = sm_u, sb = sm_u + ABUF_H * 2;
#pragma unroll
        for (int j = 0; j < 4; j++) {
            int c = tid + 256 * j;
            int arow = c >> 3, acol = (c & 7) * 8;
            CP16(sa + (arow * LDA + acol) * 2,
                 A + (size_t)(m0 + arow) * HD + acol);
            int brow = c >> 4, bcol = (c & 15) * 8;
            CP16(sb + (brow * LDB + bcol) * 2,
                 B + (size_t)brow * HD + n0 + bcol);
        }
        CPCOMMIT();
    }

    int buf = 0;
    for (int kt = 0; kt < KT; kt++) {
        if (kt + 1 < KT) {
            const int k0 = (kt + 1) * BK;
            uint32_t base = sm_u + (buf ^ 1) * BUF_H * 2;
            uint32_t sa = base, sb = base + ABUF_H * 2;
#pragma unroll
            for (int j = 0; j < 4; j++) {
                int c = tid + 256 * j;
                int arow = c >> 3, acol = (c & 7) * 8;
                CP16(sa + (arow * LDA + acol) * 2,
                     A + (size_t)(m0 + arow) * HD + k0 + acol);
                int brow = c >> 4, bcol = (c & 15) * 8;
                CP16(sb + (brow * LDB + bcol) * 2,
                     B + (size_t)(k0 + brow) * HD + n0 + bcol);
            }
            CPCOMMIT();
            CPWAIT(1);
        } else {
            CPWAIT(0);
        }
        __syncthreads();

        const __half* sa = sm + buf * BUF_H;
        const __half* sb = sa + ABUF_H;
        const __half* Abase = sa + (wm * 64) * LDA;
        const __half* Bbase = sb + wn * 32;
#pragma unroll
        for (int kk = 0; kk < 4; kk++) {
            wmma::fragment<wmma::matrix_b, 16, 16, 16, __half, wmma::row_major> bf[2];
#pragma unroll
            for (int j = 0; j < 2; j++)
                wmma::load_matrix_sync(bf[j], Bbase + kk * 16 * LDB + j * 16, LDB);
#pragma unroll
            for (int i = 0; i < 4; i++) {
                wmma::fragment<wmma::matrix_a, 16, 16, 16, __half, wmma::row_major> af;
                wmma::load_matrix_sync(af, Abase + i * 16 * LDA + kk * 16, LDA);
                wmma::mma_sync(cf[i][0], af, bf[0], cf[i][0]);
                wmma::mma_sync(cf[i][1], af, bf[1], cf[i][1]);
            }
        }
        __syncthreads();
        buf ^= 1;
    }

    // ---- epilogue: accumulators -> smem fp32 C tile (128x128) ----
    float* cb = (float*)smraw;
#pragma unroll
    for (int i = 0; i < 4; i++)
#pragma unroll
        for (int j = 0; j < 2; j++)
            wmma::store_matrix_sync(cb + (wm * 64 + i * 16) * 128 + wn * 32 + j * 16,
                                    cf[i][j], 128, wmma::mem_row_major);

    float* sbias = cb + 128 * 128;
    if (tid < 128) sbias[tid] = bias[n0 + tid];
    float* sv = sbias + 128;
    if (MODE == 2) {
        for (int j = tid; j < 384; j += 256)
            sv[j] = V[((size_t)e * 3 + (j >> 7)) * HD + n0 + (j & 127)];
    }
    __syncthreads();

    if (MODE < 2) {
#pragma unroll
        for (int j = 0; j < 16; j++) {
            int i = tid + 256 * j;
            int r = i >> 5, col = (i & 31) * 4;
            float v0 = cb[r * 128 + col + 0] + sbias[col + 0];
            float v1 = cb[r * 128 + col + 1] + sbias[col + 1];
            float v2 = cb[r * 128 + col + 2] + sbias[col + 2];
            float v3 = cb[r * 128 + col + 3] + sbias[col + 3];
            if (MODE == 0) {
                v0 = fmaxf(v0, 0.f); v1 = fmaxf(v1, 0.f);
                v2 = fmaxf(v2, 0.f); v3 = fmaxf(v3, 0.f);
            }
            __half2 lo = __floats2half2_rn(v0, v1);
            __half2 hi = __floats2half2_rn(v2, v3);
            __half* dst = Ch + (size_t)(m0 + r) * HD + n0 + col;
            *(__half2*)(dst)     = lo;
            *(__half2*)(dst + 2) = hi;
        }
    } else {
        const int row = tid >> 1, half_ = (tid & 1) * 64;
        float p0 = 0.f, p1 = 0.f, p2 = 0.f;
        const float* crow = cb + row * 128 + half_;
#pragma unroll 16
        for (int col = 0; col < 64; col++) {
            float h = fmaxf(crow[col] + sbias[half_ + col], 0.0f);
            p0 = fmaf(h, sv[half_ + col],       p0);
            p1 = fmaf(h, sv[128 + half_ + col], p1);
            p2 = fmaf(h, sv[256 + half_ + col], p2);
        }
        p0 += __shfl_xor_sync(0xffffffffu, p0, 1);
        p1 += __shfl_xor_sync(0xffffffffu, p1, 1);
        p2 += __shfl_xor_sync(0xffffffffu, p2, 1);
        if (!(tid & 1)) {
            float* Sp = S + (size_t)(m0 + row) * 18 + e * 3;
            atomicAdd(Sp + 0, p0);
            atomicAdd(Sp + 1, p1);
            atomicAdd(Sp + 2, p2);
        }
    }
}

// ---------------- v[e][t][f] = sum_o W2[e,f,o] * tw[t,o] ---------------------
__global__ void vker(const float* __restrict__ w2, const float* __restrict__ tw,
                     float* __restrict__ v)
{
    int w = (blockIdx.x * blockDim.x + threadIdx.x) >> 5;
    int lane = threadIdx.x & 31;
    if (w >= NE * NT * HD) return;
    int e = w / (NT * HD);
    int r = w % (NT * HD);
    int t = r / HD;
    int f = r % HD;
    const float* row = w2 + ((size_t)e * HD + f) * HD;
    const float* tv  = tw + (size_t)t * HD;
    float s = 0.f;
    for (int o = lane; o < HD; o += 32) s = fmaf(row[o], tv[o], s);
#pragma unroll
    for (int off = 16; off; off >>= 1) s += __shfl_xor_sync(0xffffffffu, s, off);
    if (lane == 0) v[w] = s;
}

// ---------------- c[e*3+t] = tw[t] · b2[e] ----------------------------------
__global__ void cker(const float* __restrict__ b2, const float* __restrict__ tw,
                     float* __restrict__ c)
{
    int w = threadIdx.x >> 5;
    int lane = threadIdx.x & 31;
    if (w >= 18) return;
    int e = w / 3, t = w % 3;
    float s = 0.f;
    for (int o = lane; o < HD; o += 32)
        s = fmaf(b2[(size_t)e * HD + o], tw[(size_t)t * HD + o], s);
#pragma unroll
    for (int off = 16; off; off >>= 1) s += __shfl_xor_sync(0xffffffffu, s, off);
    if (lane == 0) c[w] = s;
}

// ---------------- per-(b,t) max over candidates ------------------------------
__global__ void maxs_kernel(const float* __restrict__ scores, float* __restrict__ maxs)
{
    int i = threadIdx.x;
    if (i >= NB * NT) return;
    int b = i / NT, t = i % NT;
    float m = -1e30f;
    for (int cdx = 0; cdx < NC; cdx++)
        m = fmaxf(m, scores[(size_t)b * NC * NT + cdx * NT + t]);
    maxs[i] = m;
}

// ---------------- gate logits: glog[n][t*6+e] = x[n]·wg[t,:,e] --------------
__global__ void glog_kernel(const __half* __restrict__ x, const float* __restrict__ wg,
                            float* __restrict__ glog)
{
    __shared__ float wgs[512 * 18];
    const int tid = threadIdx.x, lane = tid & 31, w = tid >> 5;
    for (int p = 0; p < 2; p++) {
        const int hb = p * 512;
        __syncthreads();
        for (int idx = tid; idx < 512 * 18; idx += blockDim.x) {
            int h = idx / 18, j = idx % 18;
            int t = j / 6, ee = j % 6;
            wgs[idx] = wg[(size_t)t * HD * NE + (size_t)(hb + h) * NE + ee];
        }
        __syncthreads();
        for (int i = 0; i < 16; i++) {
            int n = blockIdx.x * 128 + i * 8 + w;
            float acc[18];
#pragma unroll
            for (int j = 0; j < 18; j++) acc[j] = 0.f;
            const __half* xr = x + (size_t)n * HD + hb;
            for (int h = lane; h < 512; h += 32) {
                float xv = __half2float(xr[h]);
                const float* ws = &wgs[h * 18];
#pragma unroll
                for (int j = 0; j < 18; j++) acc[j] = fmaf(xv, ws[j], acc[j]);
            }
#pragma unroll
            for (int j = 0; j < 18; j++) {
#pragma unroll
                for (int off = 16; off; off >>= 1)
                    acc[j] += __shfl_xor_sync(0xffffffffu, acc[j], off);
            }
            if (lane == 0) {
                float* o = glog + (size_t)n * 18;
                if (p == 0) {
#pragma unroll
                    for (int j = 0; j < 18; j++) o[j] = acc[j];
                } else {
#pragma unroll
                    for (int j = 0; j < 18; j++) o[j] += acc[j];
                }
            }
        }
    }
}

// ---------------- per-token: top3/softmax, z, BCE, preds, imp/load ----------
__global__ void token_kernel(const float* __restrict__ glog, const float* __restrict__ s,
                             const float* __restrict__ c, const float* __restrict__ scores,
                             const float* __restrict__ maxs, const float* __restrict__ tb,
                             float* __restrict__ stats, float* __restrict__ preds)
{
    __shared__ float simp[18], sld[18], red[256];
    const int tid = threadIdx.x;
    if (tid < 18) { simp[tid] = 0.f; sld[tid] = 0.f; }
    __syncthreads();

    const int n = blockIdx.x * 256 + tid;
    const int b = n >> 6, cdx = n & 63;

    float l[18];
    const float* gl = glog + (size_t)n * 18;
#pragma unroll
    for (int j = 0; j < 18; j++) l[j] = gl[j];
    const float* sr = s + (size_t)n * 18;

    float bsum = 0.f, zsum = 0.f;
#pragma unroll
    for (int t = 0; t < 3; t++) {
        const float* lt = l + t * 6;
        float sv0 = 0, sv1 = 0, sv2 = 0;
        int se0 = 0, se1 = 0, se2 = 0, cnt = 0;
#pragma unroll
        for (int e = 0; e < 6; e++) {
            int beats = 0;
#pragma unroll
            for (int j = 0; j < 6; j++)
                beats += (lt[j] > lt[e]) || (lt[j] == lt[e] && j < e);
            if (beats < 3) {
                if (cnt == 0)      { sv0 = lt[e]; se0 = e; }
                else if (cnt == 1) { sv1 = lt[e]; se1 = e; }
                else               { sv2 = lt[e]; se2 = e; }
                cnt++;
            }
        }
        float m  = fmaxf(sv0, fmaxf(sv1, sv2));
        float g0 = expf(sv0 - m), g1 = expf(sv1 - m), g2 = expf(sv2 - m);
        float inv = 1.f / (g0 + g1 + g2);
        g0 *= inv; g1 *= inv; g2 *= inv;

        float zt = tb[t];
        zt = fmaf(g0, sr[se0 * 3 + t] + c[se0 * 3 + t], zt);
        zt = fmaf(g1, sr[se1 * 3 + t] + c[se1 * 3 + t], zt);
        zt = fmaf(g2, sr[se2 * 3 + t] + c[se2 * 3 + t], zt);

        atomicAdd(&simp[t * 6 + se0], g0);
        atomicAdd(&simp[t * 6 + se1], g1);
        atomicAdd(&simp[t * 6 + se2], g2);
        atomicAdd(&sld[t * 6 + se0], 1.f);
        atomicAdd(&sld[t * 6 + se1], 1.f);
        atomicAdd(&sld[t * 6 + se2], 1.f);

        float sc  = scores[(size_t)b * NC * NT + cdx * NT + t];
        float lab = (sc == maxs[b * NT + t]) ? 1.f : 0.f;
        bsum += fmaxf(zt, 0.f) - zt * lab + log1pf(expf(-fabsf(zt)));
        zsum += zt;
    }
    preds[n] = 1.f / (1.f + expf(-zsum * (1.f / 3.f)));

    red[tid] = bsum;
    __syncthreads();
    for (int off = 128; off; off >>= 1) {
        if (tid < off) red[tid] += red[tid + off];
        __syncthreads();
    }
    if (tid == 0) atomicAdd(&stats[36], red[0]);
    if (tid < 18) {
        atomicAdd(&stats[tid], simp[tid]);
        atomicAdd(&stats[18 + tid], sld[tid]);
    }
}

// ---------------- final scalar: loss = bce + 1e-2 * sum cv^2 -----------------
__global__ void final_kernel(const float* __restrict__ stats, float* __restrict__ out)
{
    if (threadIdx.x == 0) {
        float aux = 0.f;
        for (int t = 0; t < 3; t++) {
            for (int which = 0; which < 2; which++) {
                const float* v = stats + which * 18 + t * 6;
                float mean = 0.f;
                for (int e = 0; e < 6; e++) mean += v[e];
                mean *= (1.f / 6.f);
                float var = 0.f;
                for (int e = 0; e < 6; e++) {
                    float d = v[e] - mean;
                    var += d * d;
                }
                var *= (1.f / 5.f);
                aux += var / (mean * mean + 1e-10f);
            }
        }
        out[0] = stats[36] * (1.f / (NB * NC * NT)) + 0.01f * aux;
    }
}

// -----------------------------------------------------------------------------
extern "C" void kernel_launch(void* const* d_in, const int* in_sizes, int n_in,
                              void* d_out, int out_size)
{
    const float* encs   = (const float*)d_in[0];
    const float* scores = (const float*)d_in[1];
    const float* fc1_w  = (const float*)d_in[2];
    const float* fc1_b  = (const float*)d_in[3];
    const float* fc2_w  = (const float*)d_in[4];
    const float* fc2_b  = (const float*)d_in[5];
    const float* w_gate = (const float*)d_in[6];
    const float* ew1    = (const float*)d_in[7];
    const float* eb1    = (const float*)d_in[8];
    const float* ew2    = (const float*)d_in[9];
    const float* eb2    = (const float*)d_in[10];
    const float* tw     = (const float*)d_in[11];
    const float* tb     = (const float*)d_in[12];

    __half *he, *hw, *t1h, *xh;
    float *glog, *s, *v, *c, *maxs, *stats;
    cudaGetSymbolAddress((void**)&he, g_he);
    cudaGetSymbolAddress((void**)&hw, g_hw);
    cudaGetSymbolAddress((void**)&t1h, g_t1h);
    cudaGetSymbolAddress((void**)&xh, g_xh);
    cudaGetSymbolAddress((void**)&glog, g_glog);
    cudaGetSymbolAddress((void**)&s, g_s);
    cudaGetSymbolAddress((void**)&v, g_v);
    cudaGetSymbolAddress((void**)&c, g_c);
    cudaGetSymbolAddress((void**)&maxs, g_maxs);
    cudaGetSymbolAddress((void**)&stats, g_stats);

    float* outf  = (float*)d_out;
    float* preds = outf + (out_size - NTOK);

    cudaFuncSetAttribute(wgemm<0>, cudaFuncAttributeMaxDynamicSharedMemorySize, SMEM_BYTES);
    cudaFuncSetAttribute(wgemm<1>, cudaFuncAttributeMaxDynamicSharedMemorySize, SMEM_BYTES);
    cudaFuncSetAttribute(wgemm<2>, cudaFuncAttributeMaxDynamicSharedMemorySize, SMEM_BYTES);

    cudaMemsetAsync(s, 0, (size_t)NTOK * 18 * sizeof(float), 0);
    cudaMemsetAsync(stats, 0, 37 * sizeof(float), 0);

    // fp32 -> fp16 conversions
    const int NA = NTOK * HD;          // 8.4M (encs)
    const int NW = HD * HD;            // 1M per matrix
    h2kern<<<(NA / 4 + 255) / 256, 256>>>(encs, he, NA);
    h2kern<<<(NW / 4 + 255) / 256, 256>>>(fc1_w, hw, NW);
    h2kern<<<(NW / 4 + 255) / 256, 256>>>(fc2_w, hw + (size_t)NW, NW);
    h2kern<<<(6 * NW / 4 + 255) / 256, 256>>>(ew1, hw + 2 * (size_t)NW, 6 * NW);

    // small precomputes (independent of GEMMs)
    vker<<<(NE * NT * HD * 32 + 255) / 256, 256>>>(ew2, tw, v);
    cker<<<1, 576>>>(eb2, tw, c);
    maxs_kernel<<<1, 384>>>(scores, maxs);

    // shared bottom (fp16 wmma)
    wgemm<0><<<dim3(8, 64, 1), 256, SMEM_BYTES>>>(he, hw, fc1_b, t1h, nullptr, nullptr);
    wgemm<1><<<dim3(8, 64, 1), 256, SMEM_BYTES>>>(t1h, hw + (size_t)NW, fc2_b, xh,
                                                  nullptr, nullptr);
    // gate logits
    glog_kernel<<<64, 256>>>(xh, w_gate, glog);
    // experts: layer-1 GEMM fused with tower-projected reduction (layer-2 eliminated)
    wgemm<2><<<dim3(8, 64, 6), 256, SMEM_BYTES>>>(xh, hw + 2 * (size_t)NW, eb1,
                                                  nullptr, v, s);
    // per-token gating + loss + preds
    token_kernel<<<32, 256>>>(glog, s, c, scores, maxs, tb, stats, preds);
    if (out_size > NTOK) final_kernel<<<1, 32>>>(stats, outf);
}

// round 6
// speedup vs baseline: 6.1339x; 1.2256x over previous
#include <cuda_runtime.h>
#include <cuda_fp16.h>
#include <math.h>
#include <stdint.h>
#include <mma.h>

using namespace nvcuda;

#define NTOK 8192
#define HD   1024
#define NT   3
#define NE   6
#define NB   128
#define NC   64

// GEMM tiling (fp16 inputs, fp32 accumulate)
#define BM 128
#define BN 128
#define BK 64
#define KT (HD / BK)
#define LDA 72                        // 64 + 8 halves pad
#define LDB 136                       // 128 + 8 halves pad
#define ABUF_H (BM * LDA)             // 9216 halves
#define BBUF_H (BK * LDB)             // 8704 halves
#define BUF_H  (ABUF_H + BBUF_H)      // 17920 halves (35840 B/stage)
#define NSTAGE 3
#define SMEM_BYTES (NSTAGE * BUF_H * 2)  // 107520 B (covers 75264 B epilogue)

// ---------------- scratch (device globals; no allocs allowed) ----------------
__device__ __half g_he[NTOK * HD];     // encs fp16
__device__ __half g_hw[8 * HD * HD];   // fp16 weights: [0]=fc1 [1]=fc2 [2..7]=ew1
__device__ __half g_t1h[NTOK * HD];    // relu(encs@fc1+b1) fp16
__device__ __half g_xh[NTOK * HD];     // shared-bottom out fp16
__device__ float g_glog[NTOK * 18];    // gate logits, [n][t*6+e]
__device__ float g_s[NTOK * 18];       // h[e,n]·v[e,t], [n][e*3+t]
__device__ float g_v[NE * NT * HD];    // v[e][t][f] = sum_o W2[e,f,o]*tw[t,o]
__device__ float g_c[18];              // c[e*3+t] = tw[t]·b2[e]
__device__ float g_maxs[NB * NT];      // per (b,t) max over candidates
__device__ float g_stats[37];          // [0..17] importance, [18..35] load, [36] bce

// ---------------- cp.async helpers ------------------------------------------
__device__ __forceinline__ uint32_t smem_u32(const void* p) {
    uint32_t a;
    asm("{ .reg .u64 t; cvta.to.shared.u64 t, %1; cvt.u32.u64 %0, t; }"
        : "=r"(a) : "l"(p));
    return a;
}
#define CP16(dst_u32, src) \
    asm volatile("cp.async.cg.shared.global [%0], [%1], 16;" \
                 :: "r"(dst_u32), "l"(src) : "memory")
#define CPCOMMIT() asm volatile("cp.async.commit_group;" ::: "memory")
#define CPWAIT(n)  asm volatile("cp.async.wait_group %0;" :: "n"(n) : "memory")

// ---------------- fp32 -> fp16 conversion -----------------------------------
__global__ void h2kern(const float* __restrict__ src, __half* __restrict__ dst, int n)
{
    int i = (blockIdx.x * blockDim.x + threadIdx.x) * 4;
    if (i < n) {
        float4 v = *(const float4*)(src + i);
        *(__half2*)(dst + i)     = __floats2half2_rn(v.x, v.y);
        *(__half2*)(dst + i + 2) = __floats2half2_rn(v.z, v.w);
    }
}

// ======================= fp16 wmma GEMM ======================================
// CTA 128x128, 4 warps (64x64 each), BK=64, 3-stage cp.async, 2 CTAs/SM.
// A: half[M,K] row-major.  B: half[K,N] row-major.
// MODE 0: Ch = half(relu(A@B + bias))
// MODE 1: Ch = half(A@B + bias); also glog[n][j] += x[n,:]·wg-slice (fused)
// MODE 2: h = relu(A@B[e] + b1[e]); S[n][e*3+t] += h · v[e][t]  (h not stored)
template <int MODE>
__global__ __launch_bounds__(128, 2)
void wgemm(const __half* __restrict__ A, const __half* __restrict__ B,
           const float* __restrict__ bias, __half* __restrict__ Ch,
           const float* __restrict__ V, float* __restrict__ S,
           const float* __restrict__ WG, float* __restrict__ GL)
{
    extern __shared__ char smraw[];
    __half* sm = (__half*)smraw;
    const int e = blockIdx.z;
    if (MODE == 2) { B += (size_t)e * HD * HD; bias += (size_t)e * HD; }
    const int m0 = blockIdx.y * BM;
    const int n0 = blockIdx.x * BN;
    const int tid = threadIdx.x;
    const int wid = tid >> 5;
    const int wm = wid & 1;        // 64-row slab
    const int wn = wid >> 1;       // 64-col slab
    const uint32_t sm_u = smem_u32(sm);

    wmma::fragment<wmma::accumulator, 16, 16, 16, float> cf[4][4];
#pragma unroll
    for (int i = 0; i < 4; i++)
#pragma unroll
        for (int j = 0; j < 4; j++) wmma::fill_fragment(cf[i][j], 0.0f);

#define ISSUE_STAGE(st, k0) do {                                              \
        uint32_t base_ = sm_u + (st) * BUF_H * 2;                             \
        uint32_t sa_ = base_, sb_ = base_ + ABUF_H * 2;                       \
        _Pragma("unroll")                                                     \
        for (int j_ = 0; j_ < 8; j_++) {                                      \
            int c_ = tid + 128 * j_;                                          \
            int ar_ = c_ >> 3, ac_ = (c_ & 7) * 8;                            \
            CP16(sa_ + (ar_ * LDA + ac_) * 2,                                 \
                 A + (size_t)(m0 + ar_) * HD + (k0) + ac_);                   \
            int br_ = c_ >> 4, bc_ = (c_ & 15) * 8;                           \
            CP16(sb_ + (br_ * LDB + bc_) * 2,                                 \
                 B + (size_t)((k0) + br_) * HD + n0 + bc_);                   \
        }                                                                     \
        CPCOMMIT();                                                           \
    } while (0)

    ISSUE_STAGE(0, 0);
    ISSUE_STAGE(1, BK);

    for (int kt = 0; kt < KT; kt++) {
        if (kt == KT - 1) { CPWAIT(0); } else { CPWAIT(1); }
        __syncthreads();
        if (kt + 2 < KT) ISSUE_STAGE((kt + 2) % NSTAGE, (kt + 2) * BK);

        const __half* sa = sm + (kt % NSTAGE) * BUF_H;
        const __half* sb = sa + ABUF_H;
        const __half* Abase = sa + (wm * 64) * LDA;
        const __half* Bbase = sb + wn * 64;
#pragma unroll
        for (int kk = 0; kk < 4; kk++) {
            wmma::fragment<wmma::matrix_b, 16, 16, 16, __half, wmma::row_major> bf[4];
#pragma unroll
            for (int j = 0; j < 4; j++)
                wmma::load_matrix_sync(bf[j], Bbase + kk * 16 * LDB + j * 16, LDB);
#pragma unroll
            for (int i = 0; i < 4; i++) {
                wmma::fragment<wmma::matrix_a, 16, 16, 16, __half, wmma::row_major> af;
                wmma::load_matrix_sync(af, Abase + i * 16 * LDA + kk * 16, LDA);
#pragma unroll
                for (int j = 0; j < 4; j++)
                    wmma::mma_sync(cf[i][j], af, bf[j], cf[i][j]);
            }
        }
    }
#undef ISSUE_STAGE
    __syncthreads();   // stage smem -> epilogue reuse

    // ---- epilogue: accumulators -> smem fp32 C tile (128x128) ----
    float* cb = (float*)smraw;
#pragma unroll
    for (int i = 0; i < 4; i++)
#pragma unroll
        for (int j = 0; j < 4; j++)
            wmma::store_matrix_sync(cb + (wm * 64 + i * 16) * 128 + wn * 64 + j * 16,
                                    cf[i][j], 128, wmma::mem_row_major);

    float* sbias = cb + 128 * 128;           // 128 floats
    sbias[tid] = bias[n0 + tid];
    float* sx = sbias + 128;                 // MODE1: wg slice [128][18]; MODE2: v [384]
    if (MODE == 1) {
        for (int idx = tid; idx < 128 * 18; idx += 128) {
            int h = idx / 18, j = idx % 18;
            int t = j / 6, ee = j % 6;
            sx[idx] = WG[(size_t)t * HD * NE + (size_t)(n0 + h) * NE + ee];
        }
    } else if (MODE == 2) {
        for (int j = tid; j < 384; j += 128)
            sx[j] = V[((size_t)e * 3 + (j >> 7)) * HD + n0 + (j & 127)];
    }
    __syncthreads();

    if (MODE < 2) {
#pragma unroll
        for (int j = 0; j < 32; j++) {
            int i = tid + 128 * j;
            int r = i >> 5, col = (i & 31) * 4;
            float v0 = cb[r * 128 + col + 0] + sbias[col + 0];
            float v1 = cb[r * 128 + col + 1] + sbias[col + 1];
            float v2 = cb[r * 128 + col + 2] + sbias[col + 2];
            float v3 = cb[r * 128 + col + 3] + sbias[col + 3];
            if (MODE == 0) {
                v0 = fmaxf(v0, 0.f); v1 = fmaxf(v1, 0.f);
                v2 = fmaxf(v2, 0.f); v3 = fmaxf(v3, 0.f);
            }
            __half* dst = Ch + (size_t)(m0 + r) * HD + n0 + col;
            *(__half2*)(dst)     = __floats2half2_rn(v0, v1);
            *(__half2*)(dst + 2) = __floats2half2_rn(v2, v3);
        }
        if (MODE == 1) {
            // fused gate logits: one row per thread
            const int r = tid;
            float acc[18];
#pragma unroll
            for (int j = 0; j < 18; j++) acc[j] = 0.f;
            const float* crow = cb + r * 128;
            for (int col = 0; col < 128; col++) {
                float xv = crow[col] + sbias[col];
                const float* ws = sx + col * 18;
#pragma unroll
                for (int j = 0; j < 18; j++) acc[j] = fmaf(xv, ws[j], acc[j]);
            }
            float* gl = GL + (size_t)(m0 + r) * 18;
#pragma unroll
            for (int j = 0; j < 18; j++) atomicAdd(gl + j, acc[j]);
        }
    } else {
        const int r = tid;
        float p0 = 0.f, p1 = 0.f, p2 = 0.f;
        const float* crow = cb + r * 128;
#pragma unroll 8
        for (int col = 0; col < 128; col++) {
            float h = fmaxf(crow[col] + sbias[col], 0.0f);
            p0 = fmaf(h, sx[col],       p0);
            p1 = fmaf(h, sx[128 + col], p1);
            p2 = fmaf(h, sx[256 + col], p2);
        }
        float* Sp = S + (size_t)(m0 + r) * 18 + e * 3;
        atomicAdd(Sp + 0, p0);
        atomicAdd(Sp + 1, p1);
        atomicAdd(Sp + 2, p2);
    }
}

// ---------------- v[e][t][f] = sum_o W2[e,f,o] * tw[t,o] ---------------------
__global__ void vker(const float* __restrict__ w2, const float* __restrict__ tw,
                     float* __restrict__ v)
{
    int w = (blockIdx.x * blockDim.x + threadIdx.x) >> 5;
    int lane = threadIdx.x & 31;
    if (w >= NE * NT * HD) return;
    int e = w / (NT * HD);
    int r = w % (NT * HD);
    int t = r / HD;
    int f = r % HD;
    const float* row = w2 + ((size_t)e * HD + f) * HD;
    const float* tv  = tw + (size_t)t * HD;
    float s = 0.f;
    for (int o = lane; o < HD; o += 32) s = fmaf(row[o], tv[o], s);
#pragma unroll
    for (int off = 16; off; off >>= 1) s += __shfl_xor_sync(0xffffffffu, s, off);
    if (lane == 0) v[w] = s;
}

// ---------------- c[e*3+t] = tw[t] · b2[e] ----------------------------------
__global__ void cker(const float* __restrict__ b2, const float* __restrict__ tw,
                     float* __restrict__ c)
{
    int w = threadIdx.x >> 5;
    int lane = threadIdx.x & 31;
    if (w >= 18) return;
    int e = w / 3, t = w % 3;
    float s = 0.f;
    for (int o = lane; o < HD; o += 32)
        s = fmaf(b2[(size_t)e * HD + o], tw[(size_t)t * HD + o], s);
#pragma unroll
    for (int off = 16; off; off >>= 1) s += __shfl_xor_sync(0xffffffffu, s, off);
    if (lane == 0) c[w] = s;
}

// ---------------- per-(b,t) max over candidates ------------------------------
__global__ void maxs_kernel(const float* __restrict__ scores, float* __restrict__ maxs)
{
    int i = threadIdx.x;
    if (i >= NB * NT) return;
    int b = i / NT, t = i % NT;
    float m = -1e30f;
    for (int cdx = 0; cdx < NC; cdx++)
        m = fmaxf(m, scores[(size_t)b * NC * NT + cdx * NT + t]);
    maxs[i] = m;
}

// ---------------- per-token: top3/softmax, z, BCE, preds, imp/load ----------
__global__ void token_kernel(const float* __restrict__ glog, const float* __restrict__ s,
                             const float* __restrict__ c, const float* __restrict__ scores,
                             const float* __restrict__ maxs, const float* __restrict__ tb,
                             float* __restrict__ stats, float* __restrict__ preds)
{
    __shared__ float simp[18], sld[18], red[256];
    const int tid = threadIdx.x;
    if (tid < 18) { simp[tid] = 0.f; sld[tid] = 0.f; }
    __syncthreads();

    const int n = blockIdx.x * 256 + tid;
    const int b = n >> 6, cdx = n & 63;

    float l[18];
    const float* gl = glog + (size_t)n * 18;
#pragma unroll
    for (int j = 0; j < 18; j++) l[j] = gl[j];
    const float* sr = s + (size_t)n * 18;

    float bsum = 0.f, zsum = 0.f;
#pragma unroll
    for (int t = 0; t < 3; t++) {
        const float* lt = l + t * 6;
        float sv0 = 0, sv1 = 0, sv2 = 0;
        int se0 = 0, se1 = 0, se2 = 0, cnt = 0;
#pragma unroll
        for (int e = 0; e < 6; e++) {
            int beats = 0;
#pragma unroll
            for (int j = 0; j < 6; j++)
                beats += (lt[j] > lt[e]) || (lt[j] == lt[e] && j < e);
            if (beats < 3) {
                if (cnt == 0)      { sv0 = lt[e]; se0 = e; }
                else if (cnt == 1) { sv1 = lt[e]; se1 = e; }
                else               { sv2 = lt[e]; se2 = e; }
                cnt++;
            }
        }
        float m  = fmaxf(sv0, fmaxf(sv1, sv2));
        float g0 = expf(sv0 - m), g1 = expf(sv1 - m), g2 = expf(sv2 - m);
        float inv = 1.f / (g0 + g1 + g2);
        g0 *= inv; g1 *= inv; g2 *= inv;

        float zt = tb[t];
        zt = fmaf(g0, sr[se0 * 3 + t] + c[se0 * 3 + t], zt);
        zt = fmaf(g1, sr[se1 * 3 + t] + c[se1 * 3 + t], zt);
        zt = fmaf(g2, sr[se2 * 3 + t] + c[se2 * 3 + t], zt);

        atomicAdd(&simp[t * 6 + se0], g0);
        atomicAdd(&simp[t * 6 + se1], g1);
        atomicAdd(&simp[t * 6 + se2], g2);
        atomicAdd(&sld[t * 6 + se0], 1.f);
        atomicAdd(&sld[t * 6 + se1], 1.f);
        atomicAdd(&sld[t * 6 + se2], 1.f);

        float sc  = scores[(size_t)b * NC * NT + cdx * NT + t];
        float lab = (sc == maxs[b * NT + t]) ? 1.f : 0.f;
        bsum += fmaxf(zt, 0.f) - zt * lab + log1pf(expf(-fabsf(zt)));
        zsum += zt;
    }
    preds[n] = 1.f / (1.f + expf(-zsum * (1.f / 3.f)));

    red[tid] = bsum;
    __syncthreads();
    for (int off = 128; off; off >>= 1) {
        if (tid < off) red[tid] += red[tid + off];
        __syncthreads();
    }
    if (tid == 0) atomicAdd(&stats[36], red[0]);
    if (tid < 18) {
        atomicAdd(&stats[tid], simp[tid]);
        atomicAdd(&stats[18 + tid], sld[tid]);
    }
}

// ---------------- final scalar: loss = bce + 1e-2 * sum cv^2 -----------------
__global__ void final_kernel(const float* __restrict__ stats, float* __restrict__ out)
{
    if (threadIdx.x == 0) {
        float aux = 0.f;
        for (int t = 0; t < 3; t++) {
            for (int which = 0; which < 2; which++) {
                const float* v = stats + which * 18 + t * 6;
                float mean = 0.f;
                for (int e = 0; e < 6; e++) mean += v[e];
                mean *= (1.f / 6.f);
                float var = 0.f;
                for (int e = 0; e < 6; e++) {
                    float d = v[e] - mean;
                    var += d * d;
                }
                var *= (1.f / 5.f);
                aux += var / (mean * mean + 1e-10f);
            }
        }
        out[0] = stats[36] * (1.f / (NB * NC * NT)) + 0.01f * aux;
    }
}

// -----------------------------------------------------------------------------
extern "C" void kernel_launch(void* const* d_in, const int* in_sizes, int n_in,
                              void* d_out, int out_size)
{
    const float* encs   = (const float*)d_in[0];
    const float* scores = (const float*)d_in[1];
    const float* fc1_w  = (const float*)d_in[2];
    const float* fc1_b  = (const float*)d_in[3];
    const float* fc2_w  = (const float*)d_in[4];
    const float* fc2_b  = (const float*)d_in[5];
    const float* w_gate = (const float*)d_in[6];
    const float* ew1    = (const float*)d_in[7];
    const float* eb1    = (const float*)d_in[8];
    const float* ew2    = (const float*)d_in[9];
    const float* eb2    = (const float*)d_in[10];
    const float* tw     = (const float*)d_in[11];
    const float* tb     = (const float*)d_in[12];

    __half *he, *hw, *t1h, *xh;
    float *glog, *s, *v, *c, *maxs, *stats;
    cudaGetSymbolAddress((void**)&he, g_he);
    cudaGetSymbolAddress((void**)&hw, g_hw);
    cudaGetSymbolAddress((void**)&t1h, g_t1h);
    cudaGetSymbolAddress((void**)&xh, g_xh);
    cudaGetSymbolAddress((void**)&glog, g_glog);
    cudaGetSymbolAddress((void**)&s, g_s);
    cudaGetSymbolAddress((void**)&v, g_v);
    cudaGetSymbolAddress((void**)&c, g_c);
    cudaGetSymbolAddress((void**)&maxs, g_maxs);
    cudaGetSymbolAddress((void**)&stats, g_stats);

    float* outf  = (float*)d_out;
    float* preds = outf + (out_size - NTOK);

    cudaFuncSetAttribute(wgemm<0>, cudaFuncAttributeMaxDynamicSharedMemorySize, SMEM_BYTES);
    cudaFuncSetAttribute(wgemm<1>, cudaFuncAttributeMaxDynamicSharedMemorySize, SMEM_BYTES);
    cudaFuncSetAttribute(wgemm<2>, cudaFuncAttributeMaxDynamicSharedMemorySize, SMEM_BYTES);

    cudaMemsetAsync(glog, 0, (size_t)NTOK * 18 * sizeof(float), 0);
    cudaMemsetAsync(s, 0, (size_t)NTOK * 18 * sizeof(float), 0);
    cudaMemsetAsync(stats, 0, 37 * sizeof(float), 0);

    // fp32 -> fp16 conversions
    const int NA = NTOK * HD;          // 8.4M (encs)
    const int NW = HD * HD;            // 1M per matrix
    h2kern<<<(NA / 4 + 255) / 256, 256>>>(encs, he, NA);
    h2kern<<<(NW / 4 + 255) / 256, 256>>>(fc1_w, hw, NW);
    h2kern<<<(NW / 4 + 255) / 256, 256>>>(fc2_w, hw + (size_t)NW, NW);
    h2kern<<<(6 * NW / 4 + 255) / 256, 256>>>(ew1, hw + 2 * (size_t)NW, 6 * NW);

    // small precomputes (independent of GEMMs)
    vker<<<(NE * NT * HD * 32 + 255) / 256, 256>>>(ew2, tw, v);
    cker<<<1, 576>>>(eb2, tw, c);
    maxs_kernel<<<1, 384>>>(scores, maxs);

    // shared bottom (fp16 wmma); fc2 fuses gate-logit accumulation
    wgemm<0><<<dim3(8, 64, 1), 128, SMEM_BYTES>>>(he, hw, fc1_b, t1h,
                                                  nullptr, nullptr, nullptr, nullptr);
    wgemm<1><<<dim3(8, 64, 1), 128, SMEM_BYTES>>>(t1h, hw + (size_t)NW, fc2_b, xh,
                                                  nullptr, nullptr, w_gate, glog);
    // experts: layer-1 GEMM fused with tower-projected reduction (layer-2 eliminated)
    wgemm<2><<<dim3(8, 64, 6), 128, SMEM_BYTES>>>(xh, hw + 2 * (size_t)NW, eb1, nullptr,
                                                  v, s, nullptr, nullptr);
    // per-token gating + loss + preds
    token_kernel<<<32, 256>>>(glog, s, c, scores, maxs, tb, stats, preds);
    if (out_size > NTOK) final_kernel<<<1, 32>>>(stats, outf);
}

// round 8
// speedup vs baseline: 6.3845x; 1.0408x over previous
#include <cuda_runtime.h>
#include <cuda_fp16.h>
#include <math.h>
#include <stdint.h>
#include <mma.h>

using namespace nvcuda;

#define NTOK 8192
#define HD   1024
#define NT   3
#define NE   6
#define NB   128
#define NC   64

// GEMM tiling (fp16 inputs, fp32 accumulate)
#define BM 128
#define BN 128
#define BK 64
#define KT (HD / BK)
#define LDA 72                        // 64 + 8 halves pad
#define LDB 136                       // 128 + 8 halves pad
#define ABUF_H (BM * LDA)             // 9216 halves
#define BBUF_H (BK * LDB)             // 8704 halves
#define BUF_H  (ABUF_H + BBUF_H)      // 17920 halves (35840 B/stage)
#define NSTAGE 3
#define SMEM_BYTES (NSTAGE * BUF_H * 2)  // 107520 B (covers 75264 B epilogue)

// ---------------- scratch (device globals; no allocs allowed) ----------------
__device__ __half g_he[NTOK * HD];     // encs fp16
__device__ __half g_hw[8 * HD * HD];   // fp16 weights: [0]=fc1 [1]=fc2 [2..7]=ew1
__device__ __half g_t1h[NTOK * HD];    // relu(encs@fc1+b1) fp16
__device__ __half g_xh[NTOK * HD];     // shared-bottom out fp16
__device__ float g_glog[NTOK * 18];    // gate logits, [n][t*6+e]
__device__ float g_s[NTOK * 18];       // h[e,n]·v[e,t], [n][e*3+t]
__device__ float g_v[NE * NT * HD];    // v[e][t][f] = sum_o W2[e,f,o]*tw[t,o]
__device__ float g_c[18];              // c[e*3+t] = tw[t]·b2[e]
__device__ float g_maxs[NB * NT];      // per (b,t) max over candidates
__device__ float g_stats[37];          // [0..17] importance, [18..35] load, [36] bce

// ---------------- cp.async helpers ------------------------------------------
__device__ __forceinline__ uint32_t smem_u32(const void* p) {
    uint32_t a;
    asm("{ .reg .u64 t; cvta.to.shared.u64 t, %1; cvt.u32.u64 %0, t; }"
        : "=r"(a) : "l"(p));
    return a;
}
#define CP16(dst_u32, src) \
    asm volatile("cp.async.cg.shared.global [%0], [%1], 16;" \
                 :: "r"(dst_u32), "l"(src) : "memory")
#define CPCOMMIT() asm volatile("cp.async.commit_group;" ::: "memory")
#define CPWAIT(n)  asm volatile("cp.async.wait_group %0;" :: "n"(n) : "memory")

// ================= fused prep kernel (one launch, block-range dispatch) ======
// ranges (blocks of 256 threads):
//   [0, 8192)           encs fp32 -> fp16                (1024 elems/block)
//   [8192, 9216)        fc1_w -> hw[0]
//   [9216, 10240)       fc2_w -> hw[1]
//   [10240, 16384)      ew1   -> hw[2..7]
//   [16384, 18688)      vker: v[w] = W2[e,f,:]·tw[t,:]   (8 outputs/block)
//   [18688, 18976)      zero glog (first half) and s (second half)
//   18976               stats zero + cker
//   18977               maxs
#define PB_ENCS   0
#define PB_W1     8192
#define PB_W2     9216
#define PB_EW     10240
#define PB_VK     16384
#define PB_ZERO   18688
#define PB_MISC   18976
#define PB_MAXS   18977
#define PREP_BLOCKS 18978

__device__ __forceinline__ void conv4(const float* __restrict__ src,
                                      __half* __restrict__ dst, int base)
{
    int i = base + threadIdx.x * 4;
    float4 v = *(const float4*)(src + i);
    *(__half2*)(dst + i)     = __floats2half2_rn(v.x, v.y);
    *(__half2*)(dst + i + 2) = __floats2half2_rn(v.z, v.w);
}

__global__ __launch_bounds__(256)
void prep_kernel(const float* __restrict__ encs, const float* __restrict__ fc1_w,
                 const float* __restrict__ fc2_w, const float* __restrict__ ew1,
                 const float* __restrict__ ew2, const float* __restrict__ eb2,
                 const float* __restrict__ tw, const float* __restrict__ scores,
                 __half* __restrict__ he, __half* __restrict__ hw,
                 float* __restrict__ glog, float* __restrict__ s,
                 float* __restrict__ stats, float* __restrict__ v,
                 float* __restrict__ c, float* __restrict__ maxs)
{
    const int blk = blockIdx.x;
    const int tid = threadIdx.x;
    const size_t NW = (size_t)HD * HD;

    if (blk < PB_W1) {
        conv4(encs, he, (blk - PB_ENCS) * 1024);
    } else if (blk < PB_W2) {
        conv4(fc1_w, hw, (blk - PB_W1) * 1024);
    } else if (blk < PB_EW) {
        conv4(fc2_w, hw + NW, (blk - PB_W2) * 1024);
    } else if (blk < PB_VK) {
        conv4(ew1, hw + 2 * NW, (blk - PB_EW) * 1024);
    } else if (blk < PB_ZERO) {
        // vker: one warp per output, 8 outputs/block
        int w = (blk - PB_VK) * 8 + (tid >> 5);
        int lane = tid & 31;
        if (w < NE * NT * HD) {
            int e = w / (NT * HD);
            int r = w % (NT * HD);
            int t = r / HD;
            int f = r % HD;
            const float* row = ew2 + ((size_t)e * HD + f) * HD;
            const float* tv  = tw + (size_t)t * HD;
            float acc = 0.f;
            for (int o = lane; o < HD; o += 32) acc = fmaf(row[o], tv[o], acc);
#pragma unroll
            for (int off = 16; off; off >>= 1)
                acc += __shfl_xor_sync(0xffffffffu, acc, off);
            if (lane == 0) v[w] = acc;
        }
    } else if (blk < PB_MISC) {
        // zero glog (first 144 blocks) and s (next 144): each 147456 floats
        int lb = blk - PB_ZERO;
        float* dst = (lb < 144) ? glog : s;
        int base = (lb % 144) * 1024 + tid * 4;
        *(float4*)(dst + base) = make_float4(0.f, 0.f, 0.f, 0.f);
    } else if (blk == PB_MISC) {
        if (tid < 37) stats[tid] = 0.f;
        // cker: warp w handles outputs w, w+8, w+16
        int wrp = tid >> 5, lane = tid & 31;
#pragma unroll
        for (int rep = 0; rep < 3; rep++) {
            int j = wrp + rep * 8;
            if (j < 18) {
                int e = j / 3, t = j % 3;
                float acc = 0.f;
                for (int o = lane; o < HD; o += 32)
                    acc = fmaf(eb2[(size_t)e * HD + o], tw[(size_t)t * HD + o], acc);
#pragma unroll
                for (int off = 16; off; off >>= 1)
                    acc += __shfl_xor_sync(0xffffffffu, acc, off);
                if (lane == 0) c[j] = acc;
            }
        }
    } else {
        // maxs: per (b,t) max over candidates; 384 outputs, 256 threads
        for (int i = tid; i < NB * NT; i += 256) {
            int b = i / NT, t = i % NT;
            float m = -1e30f;
            for (int cdx = 0; cdx < NC; cdx++)
                m = fmaxf(m, scores[(size_t)b * NC * NT + cdx * NT + t]);
            maxs[i] = m;
        }
    }
}

// ======================= fp16 wmma GEMM ======================================
// CTA 128x128, 4 warps (64x64 each), BK=64, 3-stage cp.async, 2 CTAs/SM.
// A: half[M,K] row-major.  B: half[K,N] row-major.
// MODE 0: Ch = half(relu(A@B + bias))
// MODE 1: Ch = half(A@B + bias); also glog[n][j] += x[n,:]·wg-slice (fused)
// MODE 2: h = relu(A@B[e] + b1[e]); S[n][e*3+t] += h · v[e][t]  (h not stored)
template <int MODE>
__global__ __launch_bounds__(128, 2)
void wgemm(const __half* __restrict__ A, const __half* __restrict__ B,
           const float* __restrict__ bias, __half* __restrict__ Ch,
           const float* __restrict__ V, float* __restrict__ S,
           const float* __restrict__ WG, float* __restrict__ GL)
{
    extern __shared__ char smraw[];
    __half* sm = (__half*)smraw;
    const int e = blockIdx.z;
    if (MODE == 2) { B += (size_t)e * HD * HD; bias += (size_t)e * HD; }
    const int m0 = blockIdx.y * BM;
    const int n0 = blockIdx.x * BN;
    const int tid = threadIdx.x;
    const int wid = tid >> 5;
    const int wm = wid & 1;        // 64-row slab
    const int wn = wid >> 1;       // 64-col slab
    const uint32_t sm_u = smem_u32(sm);

    wmma::fragment<wmma::accumulator, 16, 16, 16, float> cf[4][4];
#pragma unroll
    for (int i = 0; i < 4; i++)
#pragma unroll
        for (int j = 0; j < 4; j++) wmma::fill_fragment(cf[i][j], 0.0f);

#define ISSUE_STAGE(st, k0) do {                                              \
        uint32_t base_ = sm_u + (st) * BUF_H * 2;                             \
        uint32_t sa_ = base_, sb_ = base_ + ABUF_H * 2;                       \
        _Pragma("unroll")                                                     \
        for (int j_ = 0; j_ < 8; j_++) {                                      \
            int c_ = tid + 128 * j_;                                          \
            int ar_ = c_ >> 3, ac_ = (c_ & 7) * 8;                            \
            CP16(sa_ + (ar_ * LDA + ac_) * 2,                                 \
                 A + (size_t)(m0 + ar_) * HD + (k0) + ac_);                   \
            int br_ = c_ >> 4, bc_ = (c_ & 15) * 8;                           \
            CP16(sb_ + (br_ * LDB + bc_) * 2,                                 \
                 B + (size_t)((k0) + br_) * HD + n0 + bc_);                   \
        }                                                                     \
        CPCOMMIT();                                                           \
    } while (0)

    ISSUE_STAGE(0, 0);
    ISSUE_STAGE(1, BK);

    for (int kt = 0; kt < KT; kt++) {
        if (kt == KT - 1) { CPWAIT(0); } else { CPWAIT(1); }
        __syncthreads();
        if (kt + 2 < KT) ISSUE_STAGE((kt + 2) % NSTAGE, (kt + 2) * BK);

        const __half* sa = sm + (kt % NSTAGE) * BUF_H;
        const __half* sb = sa + ABUF_H;
        const __half* Abase = sa + (wm * 64) * LDA;
        const __half* Bbase = sb + wn * 64;
#pragma unroll
        for (int kk = 0; kk < 4; kk++) {
            wmma::fragment<wmma::matrix_b, 16, 16, 16, __half, wmma::row_major> bf[4];
#pragma unroll
            for (int j = 0; j < 4; j++)
                wmma::load_matrix_sync(bf[j], Bbase + kk * 16 * LDB + j * 16, LDB);
#pragma unroll
            for (int i = 0; i < 4; i++) {
                wmma::fragment<wmma::matrix_a, 16, 16, 16, __half, wmma::row_major> af;
                wmma::load_matrix_sync(af, Abase + i * 16 * LDA + kk * 16, LDA);
#pragma unroll
                for (int j = 0; j < 4; j++)
                    wmma::mma_sync(cf[i][j], af, bf[j], cf[i][j]);
            }
        }
    }
#undef ISSUE_STAGE
    __syncthreads();   // stage smem -> epilogue reuse

    // ---- epilogue: accumulators -> smem fp32 C tile (128x128) ----
    float* cb = (float*)smraw;
#pragma unroll
    for (int i = 0; i < 4; i++)
#pragma unroll
        for (int j = 0; j < 4; j++)
            wmma::store_matrix_sync(cb + (wm * 64 + i * 16) * 128 + wn * 64 + j * 16,
                                    cf[i][j], 128, wmma::mem_row_major);

    float* sbias = cb + 128 * 128;           // 128 floats
    sbias[tid] = bias[n0 + tid];
    float* sx = sbias + 128;                 // MODE1: wg slice [128][18]; MODE2: v [384]
    if (MODE == 1) {
        for (int idx = tid; idx < 128 * 18; idx += 128) {
            int h = idx / 18, j = idx % 18;
            int t = j / 6, ee = j % 6;
            sx[idx] = WG[(size_t)t * HD * NE + (size_t)(n0 + h) * NE + ee];
        }
    } else if (MODE == 2) {
        for (int j = tid; j < 384; j += 128)
            sx[j] = V[((size_t)e * 3 + (j >> 7)) * HD + n0 + (j & 127)];
    }
    __syncthreads();

    if (MODE < 2) {
#pragma unroll
        for (int j = 0; j < 32; j++) {
            int i = tid + 128 * j;
            int r = i >> 5, col = (i & 31) * 4;
            float v0 = cb[r * 128 + col + 0] + sbias[col + 0];
            float v1 = cb[r * 128 + col + 1] + sbias[col + 1];
            float v2 = cb[r * 128 + col + 2] + sbias[col + 2];
            float v3 = cb[r * 128 + col + 3] + sbias[col + 3];
            if (MODE == 0) {
                v0 = fmaxf(v0, 0.f); v1 = fmaxf(v1, 0.f);
                v2 = fmaxf(v2, 0.f); v3 = fmaxf(v3, 0.f);
            }
            __half* dst = Ch + (size_t)(m0 + r) * HD + n0 + col;
            *(__half2*)(dst)     = __floats2half2_rn(v0, v1);
            *(__half2*)(dst + 2) = __floats2half2_rn(v2, v3);
        }
        if (MODE == 1) {
            // fused gate logits: one row per thread
            const int r = tid;
            float acc[18];
#pragma unroll
            for (int j = 0; j < 18; j++) acc[j] = 0.f;
            const float* crow = cb + r * 128;
            for (int col = 0; col < 128; col++) {
                float xv = crow[col] + sbias[col];
                const float* ws = sx + col * 18;
#pragma unroll
                for (int j = 0; j < 18; j++) acc[j] = fmaf(xv, ws[j], acc[j]);
            }
            float* gl = GL + (size_t)(m0 + r) * 18;
#pragma unroll
            for (int j = 0; j < 18; j++) atomicAdd(gl + j, acc[j]);
        }
    } else {
        const int r = tid;
        float p0 = 0.f, p1 = 0.f, p2 = 0.f;
        const float* crow = cb + r * 128;
#pragma unroll 8
        for (int col = 0; col < 128; col++) {
            float h = fmaxf(crow[col] + sbias[col], 0.0f);
            p0 = fmaf(h, sx[col],       p0);
            p1 = fmaf(h, sx[128 + col], p1);
            p2 = fmaf(h, sx[256 + col], p2);
        }
        float* Sp = S + (size_t)(m0 + r) * 18 + e * 3;
        atomicAdd(Sp + 0, p0);
        atomicAdd(Sp + 1, p1);
        atomicAdd(Sp + 2, p2);
    }
}

// ---------------- per-token: top3/softmax, z, BCE, preds, imp/load ----------
__global__ void token_kernel(const float* __restrict__ glog, const float* __restrict__ s,
                             const float* __restrict__ c, const float* __restrict__ scores,
                             const float* __restrict__ maxs, const float* __restrict__ tb,
                             float* __restrict__ stats, float* __restrict__ preds)
{
    __shared__ float simp[18], sld[18], red[256];
    const int tid = threadIdx.x;
    if (tid < 18) { simp[tid] = 0.f; sld[tid] = 0.f; }
    __syncthreads();

    const int n = blockIdx.x * 256 + tid;
    const int b = n >> 6, cdx = n & 63;

    float l[18];
    const float* gl = glog + (size_t)n * 18;
#pragma unroll
    for (int j = 0; j < 18; j++) l[j] = gl[j];
    const float* sr = s + (size_t)n * 18;

    float bsum = 0.f, zsum = 0.f;
#pragma unroll
    for (int t = 0; t < 3; t++) {
        const float* lt = l + t * 6;
        float sv0 = 0, sv1 = 0, sv2 = 0;
        int se0 = 0, se1 = 0, se2 = 0, cnt = 0;
#pragma unroll
        for (int e = 0; e < 6; e++) {
            int beats = 0;
#pragma unroll
            for (int j = 0; j < 6; j++)
                beats += (lt[j] > lt[e]) || (lt[j] == lt[e] && j < e);
            if (beats < 3) {
                if (cnt == 0)      { sv0 = lt[e]; se0 = e; }
                else if (cnt == 1) { sv1 = lt[e]; se1 = e; }
                else               { sv2 = lt[e]; se2 = e; }
                cnt++;
            }
        }
        float m  = fmaxf(sv0, fmaxf(sv1, sv2));
        float g0 = expf(sv0 - m), g1 = expf(sv1 - m), g2 = expf(sv2 - m);
        float inv = 1.f / (g0 + g1 + g2);
        g0 *= inv; g1 *= inv; g2 *= inv;

        float zt = tb[t];
        zt = fmaf(g0, sr[se0 * 3 + t] + c[se0 * 3 + t], zt);
        zt = fmaf(g1, sr[se1 * 3 + t] + c[se1 * 3 + t], zt);
        zt = fmaf(g2, sr[se2 * 3 + t] + c[se2 * 3 + t], zt);

        atomicAdd(&simp[t * 6 + se0], g0);
        atomicAdd(&simp[t * 6 + se1], g1);
        atomicAdd(&simp[t * 6 + se2], g2);
        atomicAdd(&sld[t * 6 + se0], 1.f);
        atomicAdd(&sld[t * 6 + se1], 1.f);
        atomicAdd(&sld[t * 6 + se2], 1.f);

        float sc  = scores[(size_t)b * NC * NT + cdx * NT + t];
        float lab = (sc == maxs[b * NT + t]) ? 1.f : 0.f;
        bsum += fmaxf(zt, 0.f) - zt * lab + log1pf(expf(-fabsf(zt)));
        zsum += zt;
    }
    preds[n] = 1.f / (1.f + expf(-zsum * (1.f / 3.f)));

    red[tid] = bsum;
    __syncthreads();
    for (int off = 128; off; off >>= 1) {
        if (tid < off) red[tid] += red[tid + off];
        __syncthreads();
    }
    if (tid == 0) atomicAdd(&stats[36], red[0]);
    if (tid < 18) {
        atomicAdd(&stats[tid], simp[tid]);
        atomicAdd(&stats[18 + tid], sld[tid]);
    }
}

// ---------------- final scalar: loss = bce + 1e-2 * sum cv^2 -----------------
__global__ void final_kernel(const float* __restrict__ stats, float* __restrict__ out)
{
    if (threadIdx.x == 0) {
        float aux = 0.f;
        for (int t = 0; t < 3; t++) {
            for (int which = 0; which < 2; which++) {
                const float* v = stats + which * 18 + t * 6;
                float mean = 0.f;
                for (int e = 0; e < 6; e++) mean += v[e];
                mean *= (1.f / 6.f);
                float var = 0.f;
                for (int e = 0; e < 6; e++) {
                    float d = v[e] - mean;
                    var += d * d;
                }
                var *= (1.f / 5.f);
                aux += var / (mean * mean + 1e-10f);
            }
        }
        out[0] = stats[36] * (1.f / (NB * NC * NT)) + 0.01f * aux;
    }
}

// -----------------------------------------------------------------------------
extern "C" void kernel_launch(void* const* d_in, const int* in_sizes, int n_in,
                              void* d_out, int out_size)
{
    const float* encs   = (const float*)d_in[0];
    const float* scores = (const float*)d_in[1];
    const float* fc1_w  = (const float*)d_in[2];
    const float* fc1_b  = (const float*)d_in[3];
    const float* fc2_w  = (const float*)d_in[4];
    const float* fc2_b  = (const float*)d_in[5];
    const float* w_gate = (const float*)d_in[6];
    const float* ew1    = (const float*)d_in[7];
    const float* eb1    = (const float*)d_in[8];
    const float* ew2    = (const float*)d_in[9];
    const float* eb2    = (const float*)d_in[10];
    const float* tw     = (const float*)d_in[11];
    const float* tb     = (const float*)d_in[12];

    __half *he, *hw, *t1h, *xh;
    float *glog, *s, *v, *c, *maxs, *stats;
    cudaGetSymbolAddress((void**)&he, g_he);
    cudaGetSymbolAddress((void**)&hw, g_hw);
    cudaGetSymbolAddress((void**)&t1h, g_t1h);
    cudaGetSymbolAddress((void**)&xh, g_xh);
    cudaGetSymbolAddress((void**)&glog, g_glog);
    cudaGetSymbolAddress((void**)&s, g_s);
    cudaGetSymbolAddress((void**)&v, g_v);
    cudaGetSymbolAddress((void**)&c, g_c);
    cudaGetSymbolAddress((void**)&maxs, g_maxs);
    cudaGetSymbolAddress((void**)&stats, g_stats);

    float* outf  = (float*)d_out;
    float* preds = outf + (out_size - NTOK);

    cudaFuncSetAttribute(wgemm<0>, cudaFuncAttributeMaxDynamicSharedMemorySize, SMEM_BYTES);
    cudaFuncSetAttribute(wgemm<1>, cudaFuncAttributeMaxDynamicSharedMemorySize, SMEM_BYTES);
    cudaFuncSetAttribute(wgemm<2>, cudaFuncAttributeMaxDynamicSharedMemorySize, SMEM_BYTES);

    const size_t NW = (size_t)HD * HD;

    // one fused head launch: conversions + precomputes + zeroing
    prep_kernel<<<PREP_BLOCKS, 256>>>(encs, fc1_w, fc2_w, ew1, ew2, eb2, tw, scores,
                                      he, hw, glog, s, stats, v, c, maxs);

    // shared bottom (fp16 wmma); fc2 fuses gate-logit accumulation
    wgemm<0><<<dim3(8, 64, 1), 128, SMEM_BYTES>>>(he, hw, fc1_b, t1h,
                                                  nullptr, nullptr, nullptr, nullptr);
    wgemm<1><<<dim3(8, 64, 1), 128, SMEM_BYTES>>>(t1h, hw + NW, fc2_b, xh,
                                                  nullptr, nullptr, w_gate, glog);
    // experts: layer-1 GEMM fused with tower-projected reduction (layer-2 eliminated)
    wgemm<2><<<dim3(8, 64, 6), 128, SMEM_BYTES>>>(xh, hw + 2 * NW, eb1, nullptr,
                                                  v, s, nullptr, nullptr);
    // per-token gating + loss + preds
    token_kernel<<<32, 256>>>(glog, s, c, scores, maxs, tb, stats, preds);
    if (out_size > NTOK) final_kernel<<<1, 32>>>(stats, outf);
}